// round 11
// baseline (speedup 1.0000x reference)
#include <cuda_runtime.h>
#include <cuda_fp16.h>
#include <math.h>
#include <stdint.h>

// Problem constants
#define Bc   2
#define Sc   2048
#define Dc   2048
#define Hc   16
#define HDc  128
#define ROTc 64
#define Mc   (Bc*Sc)
#define NQKV (3*Dc)   // 6144

// ---------------------------------------------------------------------------
// Scratch
// ---------------------------------------------------------------------------
__device__ float g_cnt[Bc*Sc];
__device__ half  g_hsh [(size_t)Mc*Dc];
__device__ half  g_wh  [(size_t)NQKV*Dc];   // packed [Wq;Wk;Wv]
__device__ half  g_woh [(size_t)Dc*Dc];
__device__ half  g_qkvh[(size_t)Mc*NQKV];
__device__ half  g_abh [(size_t)Mc*Dc];
__device__ half  g_qh  [(size_t)Mc*Dc];
__device__ half  g_kh  [(size_t)Mc*Dc];
__device__ half  g_vh  [(size_t)Mc*Dc];

// ---------------------------------------------------------------------------
// helpers
// ---------------------------------------------------------------------------
__device__ __forceinline__ uint32_t smem_u32(const void* p) {
    uint32_t a;
    asm("{ .reg .u64 t; cvta.to.shared.u64 t, %1; cvt.u32.u64 %0, t; }"
        : "=r"(a) : "l"(p));
    return a;
}
__device__ __forceinline__ uint32_t pack_h2(float lo, float hi) {
    half2 h = __floats2half2_rn(lo, hi);
    return *(uint32_t*)&h;
}
__device__ __forceinline__ void cp16(uint32_t dst, const void* src) {
    asm volatile("cp.async.cg.shared.global [%0], [%1], 16;" :: "r"(dst), "l"(src));
}
#define CP_COMMIT() asm volatile("cp.async.commit_group;" ::: "memory")
template<int N>
__device__ __forceinline__ void cp_wait() {
    asm volatile("cp.async.wait_group %0;" :: "n"(N) : "memory");
}
__device__ __forceinline__ void ldm_x4(uint32_t r[4], uint32_t addr) {
    asm volatile("ldmatrix.sync.aligned.m8n8.x4.shared.b16 {%0,%1,%2,%3}, [%4];"
        : "=r"(r[0]), "=r"(r[1]), "=r"(r[2]), "=r"(r[3]) : "r"(addr));
}
__device__ __forceinline__ void ldm_x4t(uint32_t r[4], uint32_t addr) {
    asm volatile("ldmatrix.sync.aligned.m8n8.x4.trans.shared.b16 {%0,%1,%2,%3}, [%4];"
        : "=r"(r[0]), "=r"(r[1]), "=r"(r[2]), "=r"(r[3]) : "r"(addr));
}
__device__ __forceinline__ void sts32(uint32_t addr, uint32_t v) {
    asm volatile("st.shared.b32 [%0], %1;" :: "r"(addr), "r"(v));
}
__device__ __forceinline__ void mma_fp16(float c[4], const uint32_t a[4],
                                         const uint32_t b0, const uint32_t b1) {
    asm volatile(
        "mma.sync.aligned.m16n8k16.row.col.f32.f16.f16.f32 "
        "{%0,%1,%2,%3}, {%4,%5,%6,%7}, {%8,%9}, {%0,%1,%2,%3};"
        : "+f"(c[0]), "+f"(c[1]), "+f"(c[2]), "+f"(c[3])
        : "r"(a[0]), "r"(a[1]), "r"(a[2]), "r"(a[3]),
          "r"(b0), "r"(b1));
}

// ---------------------------------------------------------------------------
// fp32 -> fp16 conversion
// ---------------------------------------------------------------------------
__global__ __launch_bounds__(256) void f32_to_f16(
    const float* __restrict__ src, half* __restrict__ dst, int n)
{
    int i = (blockIdx.x * 256 + threadIdx.x) * 8;
    for (; i < n; i += gridDim.x * 256 * 8) {
        float4 a = *(const float4*)(src + i);
        float4 b = *(const float4*)(src + i + 4);
        uint4 u = make_uint4(pack_h2(a.x, a.y), pack_h2(a.z, a.w),
                             pack_h2(b.x, b.y), pack_h2(b.z, b.w));
        *(uint4*)(dst + i) = u;
    }
}

// ---------------------------------------------------------------------------
// fp16 GEMM core: CTA tile 128x256, warp tile 64x64, BK=32,
// cp.async 4-stage pipeline with wait_group<2>.
// Swizzle: 64B rows, 16B chunk c at phys = c ^ ((row>>1)&3).
// ---------------------------------------------------------------------------
#define GBM 128
#define GBN 256
#define GBK 32
#define GA_BUF 8192u
#define GB_BUF 16384u
#define STAGES 4
#define GB_BASE ((uint32_t)STAGES * GA_BUF)            // 32768
#define GEMM_SMEM (GB_BASE + (uint32_t)STAGES * GB_BUF) // 98304

template <typename OutT>
__device__ __forceinline__ void gemm_fp16_body(
    const half* __restrict__ A, const half* __restrict__ W,
    OutT* __restrict__ C, int M, int N, int K)
{
    extern __shared__ half gsm[];
    const uint32_t S0 = smem_u32(gsm);

    const int tid  = threadIdx.x;
    const int warp = tid >> 5, lane = tid & 31;
    const int gid  = lane >> 2, tig = lane & 3;
    const int wm   = (warp >> 2) * 64, wn = (warp & 3) * 64;
    const int bm   = blockIdx.y * GBM,  bn = blockIdx.x * GBN;

    int aRow[2], aC[2]; uint32_t aDst[2];
#pragma unroll
    for (int i = 0; i < 2; i++) {
        int cid = tid + 256 * i;
        aRow[i] = cid >> 2; aC[i] = cid & 3;
        int phys = aC[i] ^ ((aRow[i] >> 1) & 3);
        aDst[i] = S0 + aRow[i] * 64 + phys * 16;
    }
    int bRow[4], bC[4]; uint32_t bDst[4];
#pragma unroll
    for (int i = 0; i < 4; i++) {
        int cid = tid + 256 * i;
        bRow[i] = cid >> 2; bC[i] = cid & 3;
        int phys = bC[i] ^ ((bRow[i] >> 1) & 3);
        bDst[i] = S0 + GB_BASE + bRow[i] * 64 + phys * 16;
    }

    uint32_t arow[4]; int axor[4];
    const int ahi = lane >> 4;
#pragma unroll
    for (int mt = 0; mt < 4; mt++) {
        int r = wm + 16 * mt + (lane & 7) + ((lane >> 3) & 1) * 8;
        arow[mt] = S0 + r * 64;
        axor[mt] = (r >> 1) & 3;
    }
    uint32_t brow[4]; int bxor[4];
    const int bhi = (lane >> 3) & 1;
#pragma unroll
    for (int n2 = 0; n2 < 4; n2++) {
        int r = wn + n2 * 16 + (lane & 7) + ((lane >> 4) & 1) * 8;
        brow[n2] = S0 + GB_BASE + r * 64;
        bxor[n2] = (r >> 1) & 3;
    }

    float acc[4][8][4];
#pragma unroll
    for (int i = 0; i < 4; i++)
#pragma unroll
        for (int j = 0; j < 8; j++)
#pragma unroll
            for (int l = 0; l < 4; l++) acc[i][j][l] = 0.f;

    const int NT = K / GBK;

    // prologue: stages 0..2
#pragma unroll
    for (int s = 0; s < 3; s++) {
#pragma unroll
        for (int i = 0; i < 2; i++)
            cp16(aDst[i] + s * GA_BUF,
                 A + (size_t)(bm + aRow[i]) * K + s * GBK + aC[i] * 8);
#pragma unroll
        for (int i = 0; i < 4; i++)
            cp16(bDst[i] + s * GB_BUF,
                 W + (size_t)(bn + bRow[i]) * K + s * GBK + bC[i] * 8);
        CP_COMMIT();
    }

    for (int kt = 0; kt < NT; kt++) {
        if (kt < NT - 2)      cp_wait<2>();
        else if (kt == NT - 2) cp_wait<1>();
        else                   cp_wait<0>();
        __syncthreads();

        if (kt + 3 < NT) {
            const int s = kt + 3;
            const uint32_t sa = (uint32_t)(s % STAGES) * GA_BUF;
            const uint32_t sb = (uint32_t)(s % STAGES) * GB_BUF;
#pragma unroll
            for (int i = 0; i < 2; i++)
                cp16(aDst[i] + sa,
                     A + (size_t)(bm + aRow[i]) * K + s * GBK + aC[i] * 8);
#pragma unroll
            for (int i = 0; i < 4; i++)
                cp16(bDst[i] + sb,
                     W + (size_t)(bn + bRow[i]) * K + s * GBK + bC[i] * 8);
            CP_COMMIT();
        }

        const uint32_t aofs = (uint32_t)(kt % STAGES) * GA_BUF;
        const uint32_t bofs = (uint32_t)(kt % STAGES) * GB_BUF;
#pragma unroll
        for (int ks = 0; ks < 2; ks++) {
            uint32_t af[4][4], bf[8][2];
#pragma unroll
            for (int mt = 0; mt < 4; mt++) {
                int chunk = 2 * ks + ahi;
                ldm_x4(af[mt], arow[mt] + aofs + (uint32_t)((chunk ^ axor[mt]) * 16));
            }
#pragma unroll
            for (int n2 = 0; n2 < 4; n2++) {
                int chunk = 2 * ks + bhi;
                uint32_t r[4];
                ldm_x4(r, brow[n2] + bofs + (uint32_t)((chunk ^ bxor[n2]) * 16));
                bf[n2*2][0] = r[0]; bf[n2*2][1] = r[1];
                bf[n2*2+1][0] = r[2]; bf[n2*2+1][1] = r[3];
            }
#pragma unroll
            for (int mt = 0; mt < 4; mt++)
#pragma unroll
                for (int nt = 0; nt < 8; nt++)
                    mma_fp16(acc[mt][nt], af[mt], bf[nt][0], bf[nt][1]);
        }
    }

    // epilogue
#pragma unroll
    for (int mt = 0; mt < 4; mt++) {
        int r0 = bm + wm + mt * 16 + gid;
#pragma unroll
        for (int nt = 0; nt < 8; nt++) {
            int c0 = bn + wn + nt * 8 + tig * 2;
            if (sizeof(OutT) == 2) {
                half* Ch = (half*)C;
                *(uint32_t*)&Ch[(size_t)r0 * N + c0]       = pack_h2(acc[mt][nt][0], acc[mt][nt][1]);
                *(uint32_t*)&Ch[(size_t)(r0 + 8) * N + c0] = pack_h2(acc[mt][nt][2], acc[mt][nt][3]);
            } else {
                float* Cf = (float*)C;
                *(float2*)&Cf[(size_t)r0 * N + c0]       = make_float2(acc[mt][nt][0], acc[mt][nt][1]);
                *(float2*)&Cf[(size_t)(r0 + 8) * N + c0] = make_float2(acc[mt][nt][2], acc[mt][nt][3]);
            }
        }
    }
}

__global__ __launch_bounds__(256) void gemm_fp16_h(
    const half* __restrict__ A, const half* __restrict__ W,
    half* __restrict__ C, int M, int N, int K)
{ gemm_fp16_body<half>(A, W, C, M, N, K); }

__global__ __launch_bounds__(256) void gemm_fp16_f(
    const half* __restrict__ A, const half* __restrict__ W,
    float* __restrict__ C, int M, int N, int K)
{ gemm_fp16_body<float>(A, W, C, M, N, K); }

// ---------------------------------------------------------------------------
// counts
// ---------------------------------------------------------------------------
__global__ __launch_bounds__(256) void counts_kernel(
    const float* __restrict__ mask, float* __restrict__ cnt)
{
    __shared__ float part[256];
    const int b = blockIdx.x;
    const int t = threadIdx.x;
    const int base = b * Sc;

    float local[8];
    float sum = 0.f;
#pragma unroll
    for (int j = 0; j < 8; j++) {
        int s = t * 8 + j;
        float kp = (mask[base + s] == 0.f) ? 1.f : 0.f;
        sum += kp;
        local[j] = sum;
    }
    part[t] = sum;
    __syncthreads();
    if (t == 0) {
        float run = 0.f;
        for (int i = 0; i < 256; i++) { float tmp = part[i]; part[i] = run; run += tmp; }
    }
    __syncthreads();
    float off = part[t];
#pragma unroll
    for (int j = 0; j < 8; j++)
        cnt[base + t * 8 + j] = off + local[j];
}

// ---------------------------------------------------------------------------
// fused post-projection: reads fused fp16 QKV [M][6144], RoPE+L2norm+mask
// for Q/K, scale V; writes fp16 Q/K/V [M][2048]
// ---------------------------------------------------------------------------
__global__ __launch_bounds__(128) void post_qkv_kernel(
    const half* __restrict__ QKV,
    half* __restrict__ Qh, half* __restrict__ Kh, half* __restrict__ Vh,
    const float* __restrict__ mask, const int* __restrict__ pos,
    const float* __restrict__ cnt, const float* __restrict__ nc)
{
    const int bsh = blockIdx.x;
    const int h  = bsh & (Hc - 1);
    const int bs = bsh >> 4;
    const int d = threadIdx.x;
    const size_t inb = (size_t)bs * NQKV + h * HDc + d;
    const size_t outb = (size_t)bs * Dc + h * HDc + d;

    __shared__ float sq[HDc], sk[HDc];
    __shared__ float redq[4], redk[4];

    float xq = __half2float(QKV[inb]);
    float xk = __half2float(QKV[inb + Dc]);
    float xv = __half2float(QKV[inb + 2 * Dc]);
    sq[d] = xq; sk[d] = xk;
    __syncthreads();

    float yq = xq, yk = xk;
    if (d < ROTc) {
        int i = d >> 1;
        float inv = powf(10000.f, -(float)(2 * i) / (float)ROTc);
        float ang = (float)pos[bs] * inv;
        float sn, cs;
        sincosf(ang, &sn, &cs);
        float oq = (d & 1) ? sq[d - 1] : sq[d + 1];
        float ok = (d & 1) ? sk[d - 1] : sk[d + 1];
        yq = (d & 1) ? (xq * cs + oq * sn) : (xq * cs - oq * sn);
        yk = (d & 1) ? (xk * cs + ok * sn) : (xk * cs - ok * sn);
    }

    float ssq = yq * yq, ssk = yk * yk;
#pragma unroll
    for (int o = 16; o; o >>= 1) {
        ssq += __shfl_xor_sync(0xffffffffu, ssq, o);
        ssk += __shfl_xor_sync(0xffffffffu, ssk, o);
    }
    if ((d & 31) == 0) { redq[d >> 5] = ssq; redk[d >> 5] = ssk; }
    __syncthreads();
    float nq = sqrtf(redq[0] + redq[1] + redq[2] + redq[3]);
    float nk = sqrtf(redk[0] + redk[1] + redk[2] + redk[3]);

    float keep = (mask[bs] == 0.f) ? 1.f : 0.f;
    Qh[outb] = __float2half(yq / fmaxf(nq, 1e-12f) * keep);
    Kh[outb] = __float2half(yk / fmaxf(nk, 1e-12f) * keep);

    float expo = 1.f / (1.f + expf(-nc[h]));
    float scale = keep / fmaxf(powf(cnt[bs], expo), 1.f);
    Vh[outb] = __float2half(xv * scale);
}

// ---------------------------------------------------------------------------
// fp16 tensor-core causal attention, q-tile 128, k-tile 64.
// 256 thr / 8 warps; warp w owns q rows [16w,16w+16), full d=128.
// Q tile [128][128] (256B rows), K/V [64][128] double-buffered, P [128][64].
// Swizzle: 16B chunk c at phys = c ^ (row&7).
// ---------------------------------------------------------------------------
#define AQ3 128
#define KT3 64
#define A3_QS  0u
#define A3_KS0 32768u
#define A3_KS1 49152u
#define A3_VS0 65536u
#define A3_VS1 81920u
#define A3_PS  98304u
#define A3_SMEM 114688

__global__ __launch_bounds__(256) void attn_fp16_128(
    const half* __restrict__ Qh, const half* __restrict__ Kh,
    const half* __restrict__ Vh, half* __restrict__ O)
{
    extern __shared__ half smh[];
    const uint32_t S0 = smem_u32(smh);

    const int bh = blockIdx.y;
    const int b = bh >> 4;
    const int h = bh & (Hc - 1);
    const int qt = gridDim.x - 1 - blockIdx.x;   // big tiles first

    const int tid  = threadIdx.x;
    const int warp = tid >> 5, lane = tid & 31;
    const int gid  = lane >> 2, tig = lane & 3;
    const int wq   = warp * 16;

    const uint32_t kbuf[2] = {A3_KS0, A3_KS1};
    const uint32_t vbuf[2] = {A3_VS0, A3_VS1};

    // K/V staging: 4 chunks/thread (64 rows x 16 chunks)
    int srow[4], sphy[4];
#pragma unroll
    for (int i = 0; i < 4; i++) {
        int cid = tid + 256 * i;
        srow[i] = cid >> 4;
        sphy[i] = (cid & 15) ^ (srow[i] & 7);
    }

    const half* Qg = Qh + ((size_t)(b * Sc + qt * AQ3)) * Dc + h * HDc;

    // prologue: stage Q (8 chunks/thread) + K/V tile 0
#pragma unroll
    for (int i = 0; i < 8; i++) {
        int cid = tid + 256 * i;
        int row = cid >> 4, c = cid & 15;
        cp16(S0 + A3_QS + row * 256 + ((c ^ (row & 7)) * 16),
             Qg + (size_t)row * Dc + c * 8);
    }
    {
        const half* Kg = Kh + ((size_t)(b * Sc)) * Dc + h * HDc;
        const half* Vg = Vh + ((size_t)(b * Sc)) * Dc + h * HDc;
#pragma unroll
        for (int i = 0; i < 4; i++) {
            int c = (tid + 256 * i) & 15;
            cp16(S0 + kbuf[0] + srow[i] * 256 + sphy[i] * 16,
                 Kg + (size_t)srow[i] * Dc + c * 8);
            cp16(S0 + vbuf[0] + srow[i] * 256 + sphy[i] * 16,
                 Vg + (size_t)srow[i] * Dc + c * 8);
        }
    }
    CP_COMMIT();

    float oacc[16][4];
#pragma unroll
    for (int i = 0; i < 16; i++)
#pragma unroll
        for (int l = 0; l < 4; l++) oacc[i][l] = 0.f;

    const int arow1 = wq + (lane & 7) + ((lane >> 3) & 1) * 8;
    const int ax1 = arow1 & 7;
    const int chi = lane >> 4;
    const int ktmax = 2 * qt + 1;

    for (int kt = 0; kt <= ktmax; kt++) {
        cp_wait<0>();
        __syncthreads();

        if (kt + 1 <= ktmax) {
            const int s = kt + 1;
            const uint32_t kb = kbuf[s & 1], vb = vbuf[s & 1];
            const half* Kg = Kh + ((size_t)(b * Sc + s * KT3)) * Dc + h * HDc;
            const half* Vg = Vh + ((size_t)(b * Sc + s * KT3)) * Dc + h * HDc;
#pragma unroll
            for (int i = 0; i < 4; i++) {
                int c = (tid + 256 * i) & 15;
                cp16(S0 + kb + srow[i] * 256 + sphy[i] * 16,
                     Kg + (size_t)srow[i] * Dc + c * 8);
                cp16(S0 + vb + srow[i] * 256 + sphy[i] * 16,
                     Vg + (size_t)srow[i] * Dc + c * 8);
            }
            CP_COMMIT();
        }

        const uint32_t kbs = S0 + kbuf[kt & 1];
        const uint32_t vbs = S0 + vbuf[kt & 1];

        // ---- phase 1: P[16q x 64k] per warp over d=128 ----
        float pacc[8][4];
#pragma unroll
        for (int i = 0; i < 8; i++)
#pragma unroll
            for (int l = 0; l < 4; l++) pacc[i][l] = 0.f;

#pragma unroll
        for (int ks = 0; ks < 8; ks++) {
            const int c0 = ks * 2 + chi;
            uint32_t a[4];
            ldm_x4(a, S0 + A3_QS + arow1 * 256 + ((c0 ^ ax1) * 16));
#pragma unroll
            for (int n2 = 0; n2 < 4; n2++) {
                int brow = n2 * 16 + (lane & 7) + ((lane >> 3) & 1) * 8;
                uint32_t r[4];
                ldm_x4(r, kbs + brow * 256 + ((c0 ^ (brow & 7)) * 16));
                mma_fp16(pacc[2*n2],   a, r[0], r[2]);
                mma_fp16(pacc[2*n2+1], a, r[1], r[3]);
            }
        }

        // mask (global indices) + store P as fp16
        const bool diag = (kt >= 2 * qt);
#pragma unroll
        for (int nt = 0; nt < 8; nt++) {
            int kl0 = nt * 8 + tig * 2;
            int q0 = wq + gid, q1 = q0 + 8;
            float v00 = pacc[nt][0], v01 = pacc[nt][1];
            float v10 = pacc[nt][2], v11 = pacc[nt][3];
            if (diag) {
                int gk0 = kt * KT3 + kl0;
                int gq0 = qt * AQ3 + q0, gq1 = gq0 + 8;
                if (gk0     > gq0) v00 = 0.f;
                if (gk0 + 1 > gq0) v01 = 0.f;
                if (gk0     > gq1) v10 = 0.f;
                if (gk0 + 1 > gq1) v11 = 0.f;
            }
            int chunk = kl0 >> 3;
            sts32(S0 + A3_PS + q0 * 128 + ((chunk ^ (q0 & 7)) * 16) + tig * 4,
                  pack_h2(v00, v01));
            sts32(S0 + A3_PS + q1 * 128 + ((chunk ^ (q1 & 7)) * 16) + tig * 4,
                  pack_h2(v10, v11));
        }
        __syncthreads();

        // ---- phase 2: O[16q x 128d] per warp over k=64 ----
#pragma unroll
        for (int ks = 0; ks < 4; ks++) {
            const int ca = ks * 2 + chi;
            uint32_t a[4];
            ldm_x4(a, S0 + A3_PS + arow1 * 128 + ((ca ^ ax1) * 16));
            const int vrow = ks * 16 + (lane & 7) + ((lane >> 3) & 1) * 8;
            const int vx = vrow & 7;
#pragma unroll
            for (int j = 0; j < 8; j++) {
                int cd = j * 2 + chi;
                uint32_t r[4];
                ldm_x4t(r, vbs + vrow * 256 + ((cd ^ vx) * 16));
                mma_fp16(oacc[2*j],   a, r[0], r[1]);
                mma_fp16(oacc[2*j+1], a, r[2], r[3]);
            }
        }
        __syncthreads();   // done with P and this K/V buffer
    }

    // epilogue: write O as fp16
    half* Og = O + ((size_t)(b * Sc + qt * AQ3)) * Dc + h * HDc;
    int q0 = wq + gid, q1 = q0 + 8;
#pragma unroll
    for (int nt = 0; nt < 16; nt++) {
        int d0 = nt * 8 + tig * 2;
        *(uint32_t*)&Og[(size_t)q0 * Dc + d0] = pack_h2(oacc[nt][0], oacc[nt][1]);
        *(uint32_t*)&Og[(size_t)q1 * Dc + d0] = pack_h2(oacc[nt][2], oacc[nt][3]);
    }
}

// ---------------------------------------------------------------------------
// launch
// ---------------------------------------------------------------------------
extern "C" void kernel_launch(void* const* d_in, const int* in_sizes, int n_in,
                              void* d_out, int out_size)
{
    const float* hs   = (const float*)d_in[0];
    const float* mask = (const float*)d_in[1];
    const int*   pos  = (const int*)  d_in[2];
    const float* Wq   = (const float*)d_in[3];
    const float* Wk   = (const float*)d_in[4];
    const float* Wv   = (const float*)d_in[5];
    const float* Wo   = (const float*)d_in[6];
    const float* nc   = (const float*)d_in[7];
    float* out = (float*)d_out;

    float *cnt;
    half *hsh, *wh, *woh, *qkvh, *abh, *qh, *kh, *vh;
    cudaGetSymbolAddress((void**)&cnt,  g_cnt);
    cudaGetSymbolAddress((void**)&hsh,  g_hsh);
    cudaGetSymbolAddress((void**)&wh,   g_wh);
    cudaGetSymbolAddress((void**)&woh,  g_woh);
    cudaGetSymbolAddress((void**)&qkvh, g_qkvh);
    cudaGetSymbolAddress((void**)&abh,  g_abh);
    cudaGetSymbolAddress((void**)&qh,   g_qh);
    cudaGetSymbolAddress((void**)&kh,   g_kh);
    cudaGetSymbolAddress((void**)&vh,   g_vh);

    cudaFuncSetAttribute(gemm_fp16_h,
                         cudaFuncAttributeMaxDynamicSharedMemorySize, GEMM_SMEM);
    cudaFuncSetAttribute(gemm_fp16_f,
                         cudaFuncAttributeMaxDynamicSharedMemorySize, GEMM_SMEM);
    cudaFuncSetAttribute(attn_fp16_128,
                         cudaFuncAttributeMaxDynamicSharedMemorySize, A3_SMEM);

    const int nHS = Mc * Dc;
    const int nW  = Dc * Dc;

    counts_kernel<<<Bc, 256>>>(mask, cnt);

    f32_to_f16<<<nHS / (256 * 8), 256>>>(hs, hsh, nHS);
    f32_to_f16<<<nW  / (256 * 8), 256>>>(Wq, wh, nW);
    f32_to_f16<<<nW  / (256 * 8), 256>>>(Wk, wh + (size_t)Dc * Dc, nW);
    f32_to_f16<<<nW  / (256 * 8), 256>>>(Wv, wh + (size_t)2 * Dc * Dc, nW);
    f32_to_f16<<<nW  / (256 * 8), 256>>>(Wo, woh, nW);

    // fused QKV GEMM: [M][2048] x [6144][2048]^T -> [M][6144] fp16
    dim3 qkvGrid(NQKV / GBN, Mc / GBM);   // (24, 32)
    gemm_fp16_h<<<qkvGrid, 256, GEMM_SMEM>>>(hsh, wh, qkvh, Mc, NQKV, Dc);

    const int nrows = Bc * Sc * Hc;
    post_qkv_kernel<<<nrows, 128>>>(qkvh, qh, kh, vh, mask, pos, cnt, nc);

    dim3 attnGrid(Sc / AQ3, Bc * Hc);     // (16, 32)
    attn_fp16_128<<<attnGrid, 256, A3_SMEM>>>(qh, kh, vh, abh);

    dim3 oGrid(Dc / GBN, Mc / GBM);       // (8, 32)
    gemm_fp16_f<<<oGrid, 256, GEMM_SMEM>>>(abh, woh, out, Mc, Dc, Dc);
}

// round 12
// speedup vs baseline: 1.0313x; 1.0313x over previous
#include <cuda_runtime.h>
#include <cuda_fp16.h>
#include <math.h>
#include <stdint.h>

// Problem constants
#define Bc   2
#define Sc   2048
#define Dc   2048
#define Hc   16
#define HDc  128
#define ROTc 64
#define Mc   (Bc*Sc)
#define NQKV (3*Dc)   // 6144

// ---------------------------------------------------------------------------
// Scratch
// ---------------------------------------------------------------------------
__device__ float g_cnt[Bc*Sc];
__device__ half  g_hsh [(size_t)Mc*Dc];
__device__ half  g_wh  [(size_t)NQKV*Dc];   // packed [Wq;Wk;Wv]
__device__ half  g_woh [(size_t)Dc*Dc];
__device__ half  g_qkvh[(size_t)Mc*NQKV];
__device__ half  g_abh [(size_t)Mc*Dc];
__device__ half  g_qh  [(size_t)Mc*Dc];
__device__ half  g_kh  [(size_t)Mc*Dc];
__device__ half  g_vh  [(size_t)Mc*Dc];

// ---------------------------------------------------------------------------
// helpers
// ---------------------------------------------------------------------------
__device__ __forceinline__ uint32_t smem_u32(const void* p) {
    uint32_t a;
    asm("{ .reg .u64 t; cvta.to.shared.u64 t, %1; cvt.u32.u64 %0, t; }"
        : "=r"(a) : "l"(p));
    return a;
}
__device__ __forceinline__ uint32_t pack_h2(float lo, float hi) {
    half2 h = __floats2half2_rn(lo, hi);
    return *(uint32_t*)&h;
}
__device__ __forceinline__ void cp16(uint32_t dst, const void* src) {
    asm volatile("cp.async.cg.shared.global [%0], [%1], 16;" :: "r"(dst), "l"(src));
}
#define CP_COMMIT() asm volatile("cp.async.commit_group;" ::: "memory")
template<int N>
__device__ __forceinline__ void cp_wait() {
    asm volatile("cp.async.wait_group %0;" :: "n"(N) : "memory");
}
__device__ __forceinline__ void ldm_x4(uint32_t r[4], uint32_t addr) {
    asm volatile("ldmatrix.sync.aligned.m8n8.x4.shared.b16 {%0,%1,%2,%3}, [%4];"
        : "=r"(r[0]), "=r"(r[1]), "=r"(r[2]), "=r"(r[3]) : "r"(addr));
}
__device__ __forceinline__ void ldm_x4t(uint32_t r[4], uint32_t addr) {
    asm volatile("ldmatrix.sync.aligned.m8n8.x4.trans.shared.b16 {%0,%1,%2,%3}, [%4];"
        : "=r"(r[0]), "=r"(r[1]), "=r"(r[2]), "=r"(r[3]) : "r"(addr));
}
__device__ __forceinline__ void sts32(uint32_t addr, uint32_t v) {
    asm volatile("st.shared.b32 [%0], %1;" :: "r"(addr), "r"(v));
}
__device__ __forceinline__ void mma_fp16(float c[4], const uint32_t a[4],
                                         const uint32_t b0, const uint32_t b1) {
    asm volatile(
        "mma.sync.aligned.m16n8k16.row.col.f32.f16.f16.f32 "
        "{%0,%1,%2,%3}, {%4,%5,%6,%7}, {%8,%9}, {%0,%1,%2,%3};"
        : "+f"(c[0]), "+f"(c[1]), "+f"(c[2]), "+f"(c[3])
        : "r"(a[0]), "r"(a[1]), "r"(a[2]), "r"(a[3]),
          "r"(b0), "r"(b1));
}

// ---------------------------------------------------------------------------
// fp32 -> fp16 conversion
// ---------------------------------------------------------------------------
__global__ __launch_bounds__(256) void f32_to_f16(
    const float* __restrict__ src, half* __restrict__ dst, int n)
{
    int i = (blockIdx.x * 256 + threadIdx.x) * 8;
    for (; i < n; i += gridDim.x * 256 * 8) {
        float4 a = *(const float4*)(src + i);
        float4 b = *(const float4*)(src + i + 4);
        uint4 u = make_uint4(pack_h2(a.x, a.y), pack_h2(a.z, a.w),
                             pack_h2(b.x, b.y), pack_h2(b.z, b.w));
        *(uint4*)(dst + i) = u;
    }
}

// ---------------------------------------------------------------------------
// fp16 GEMM core: CTA tile 128x256, warp tile 64x64, BK=32,
// cp.async 4-stage pipeline with wait_group<2>.
// Swizzle: 64B rows, 16B chunk c at phys = c ^ ((row>>1)&3).
// ---------------------------------------------------------------------------
#define GBM 128
#define GBN 256
#define GBK 32
#define GA_BUF 8192u
#define GB_BUF 16384u
#define STAGES 4
#define GB_BASE ((uint32_t)STAGES * GA_BUF)             // 32768
#define GEMM_SMEM (GB_BASE + (uint32_t)STAGES * GB_BUF) // 98304

template <typename OutT>
__device__ __forceinline__ void gemm_fp16_body(
    const half* __restrict__ A, const half* __restrict__ W,
    OutT* __restrict__ C, int M, int N, int K)
{
    extern __shared__ half gsm[];
    const uint32_t S0 = smem_u32(gsm);

    const int tid  = threadIdx.x;
    const int warp = tid >> 5, lane = tid & 31;
    const int gid  = lane >> 2, tig = lane & 3;
    const int wm   = (warp >> 2) * 64, wn = (warp & 3) * 64;
    const int bm   = blockIdx.y * GBM,  bn = blockIdx.x * GBN;

    int aRow[2], aC[2]; uint32_t aDst[2];
#pragma unroll
    for (int i = 0; i < 2; i++) {
        int cid = tid + 256 * i;
        aRow[i] = cid >> 2; aC[i] = cid & 3;
        int phys = aC[i] ^ ((aRow[i] >> 1) & 3);
        aDst[i] = S0 + aRow[i] * 64 + phys * 16;
    }
    int bRow[4], bC[4]; uint32_t bDst[4];
#pragma unroll
    for (int i = 0; i < 4; i++) {
        int cid = tid + 256 * i;
        bRow[i] = cid >> 2; bC[i] = cid & 3;
        int phys = bC[i] ^ ((bRow[i] >> 1) & 3);
        bDst[i] = S0 + GB_BASE + bRow[i] * 64 + phys * 16;
    }

    uint32_t arow[4]; int axor[4];
    const int ahi = lane >> 4;
#pragma unroll
    for (int mt = 0; mt < 4; mt++) {
        int r = wm + 16 * mt + (lane & 7) + ((lane >> 3) & 1) * 8;
        arow[mt] = S0 + r * 64;
        axor[mt] = (r >> 1) & 3;
    }
    uint32_t brow[4]; int bxor[4];
    const int bhi = (lane >> 3) & 1;
#pragma unroll
    for (int n2 = 0; n2 < 4; n2++) {
        int r = wn + n2 * 16 + (lane & 7) + ((lane >> 4) & 1) * 8;
        brow[n2] = S0 + GB_BASE + r * 64;
        bxor[n2] = (r >> 1) & 3;
    }

    float acc[4][8][4];
#pragma unroll
    for (int i = 0; i < 4; i++)
#pragma unroll
        for (int j = 0; j < 8; j++)
#pragma unroll
            for (int l = 0; l < 4; l++) acc[i][j][l] = 0.f;

    const int NT = K / GBK;

    // prologue: stages 0..2
#pragma unroll
    for (int s = 0; s < 3; s++) {
#pragma unroll
        for (int i = 0; i < 2; i++)
            cp16(aDst[i] + s * GA_BUF,
                 A + (size_t)(bm + aRow[i]) * K + s * GBK + aC[i] * 8);
#pragma unroll
        for (int i = 0; i < 4; i++)
            cp16(bDst[i] + s * GB_BUF,
                 W + (size_t)(bn + bRow[i]) * K + s * GBK + bC[i] * 8);
        CP_COMMIT();
    }

    for (int kt = 0; kt < NT; kt++) {
        if (kt < NT - 2)       cp_wait<2>();
        else if (kt == NT - 2) cp_wait<1>();
        else                   cp_wait<0>();
        __syncthreads();

        if (kt + 3 < NT) {
            const int s = kt + 3;
            const uint32_t sa = (uint32_t)(s % STAGES) * GA_BUF;
            const uint32_t sb = (uint32_t)(s % STAGES) * GB_BUF;
#pragma unroll
            for (int i = 0; i < 2; i++)
                cp16(aDst[i] + sa,
                     A + (size_t)(bm + aRow[i]) * K + s * GBK + aC[i] * 8);
#pragma unroll
            for (int i = 0; i < 4; i++)
                cp16(bDst[i] + sb,
                     W + (size_t)(bn + bRow[i]) * K + s * GBK + bC[i] * 8);
            CP_COMMIT();
        }

        const uint32_t aofs = (uint32_t)(kt % STAGES) * GA_BUF;
        const uint32_t bofs = (uint32_t)(kt % STAGES) * GB_BUF;
#pragma unroll
        for (int ks = 0; ks < 2; ks++) {
            uint32_t af[4][4], bf[8][2];
#pragma unroll
            for (int mt = 0; mt < 4; mt++) {
                int chunk = 2 * ks + ahi;
                ldm_x4(af[mt], arow[mt] + aofs + (uint32_t)((chunk ^ axor[mt]) * 16));
            }
#pragma unroll
            for (int n2 = 0; n2 < 4; n2++) {
                int chunk = 2 * ks + bhi;
                uint32_t r[4];
                ldm_x4(r, brow[n2] + bofs + (uint32_t)((chunk ^ bxor[n2]) * 16));
                bf[n2*2][0] = r[0]; bf[n2*2][1] = r[1];
                bf[n2*2+1][0] = r[2]; bf[n2*2+1][1] = r[3];
            }
#pragma unroll
            for (int mt = 0; mt < 4; mt++)
#pragma unroll
                for (int nt = 0; nt < 8; nt++)
                    mma_fp16(acc[mt][nt], af[mt], bf[nt][0], bf[nt][1]);
        }
    }

    // epilogue
#pragma unroll
    for (int mt = 0; mt < 4; mt++) {
        int r0 = bm + wm + mt * 16 + gid;
#pragma unroll
        for (int nt = 0; nt < 8; nt++) {
            int c0 = bn + wn + nt * 8 + tig * 2;
            if (sizeof(OutT) == 2) {
                half* Ch = (half*)C;
                *(uint32_t*)&Ch[(size_t)r0 * N + c0]       = pack_h2(acc[mt][nt][0], acc[mt][nt][1]);
                *(uint32_t*)&Ch[(size_t)(r0 + 8) * N + c0] = pack_h2(acc[mt][nt][2], acc[mt][nt][3]);
            } else {
                float* Cf = (float*)C;
                *(float2*)&Cf[(size_t)r0 * N + c0]       = make_float2(acc[mt][nt][0], acc[mt][nt][1]);
                *(float2*)&Cf[(size_t)(r0 + 8) * N + c0] = make_float2(acc[mt][nt][2], acc[mt][nt][3]);
            }
        }
    }
}

__global__ __launch_bounds__(256) void gemm_fp16_h(
    const half* __restrict__ A, const half* __restrict__ W,
    half* __restrict__ C, int M, int N, int K)
{ gemm_fp16_body<half>(A, W, C, M, N, K); }

__global__ __launch_bounds__(256) void gemm_fp16_f(
    const half* __restrict__ A, const half* __restrict__ W,
    float* __restrict__ C, int M, int N, int K)
{ gemm_fp16_body<float>(A, W, C, M, N, K); }

// ---------------------------------------------------------------------------
// counts
// ---------------------------------------------------------------------------
__global__ __launch_bounds__(256) void counts_kernel(
    const float* __restrict__ mask, float* __restrict__ cnt)
{
    __shared__ float part[256];
    const int b = blockIdx.x;
    const int t = threadIdx.x;
    const int base = b * Sc;

    float local[8];
    float sum = 0.f;
#pragma unroll
    for (int j = 0; j < 8; j++) {
        int s = t * 8 + j;
        float kp = (mask[base + s] == 0.f) ? 1.f : 0.f;
        sum += kp;
        local[j] = sum;
    }
    part[t] = sum;
    __syncthreads();
    if (t == 0) {
        float run = 0.f;
        for (int i = 0; i < 256; i++) { float tmp = part[i]; part[i] = run; run += tmp; }
    }
    __syncthreads();
    float off = part[t];
#pragma unroll
    for (int j = 0; j < 8; j++)
        cnt[base + t * 8 + j] = off + local[j];
}

// ---------------------------------------------------------------------------
// fused post-projection: reads fused fp16 QKV [M][6144], RoPE+L2norm+mask
// for Q/K, scale V; writes fp16 Q/K/V [M][2048]
// ---------------------------------------------------------------------------
__global__ __launch_bounds__(128) void post_qkv_kernel(
    const half* __restrict__ QKV,
    half* __restrict__ Qh, half* __restrict__ Kh, half* __restrict__ Vh,
    const float* __restrict__ mask, const int* __restrict__ pos,
    const float* __restrict__ cnt, const float* __restrict__ nc)
{
    const int bsh = blockIdx.x;
    const int h  = bsh & (Hc - 1);
    const int bs = bsh >> 4;
    const int d = threadIdx.x;
    const size_t inb = (size_t)bs * NQKV + h * HDc + d;
    const size_t outb = (size_t)bs * Dc + h * HDc + d;

    __shared__ float sq[HDc], sk[HDc];
    __shared__ float redq[4], redk[4];

    float xq = __half2float(QKV[inb]);
    float xk = __half2float(QKV[inb + Dc]);
    float xv = __half2float(QKV[inb + 2 * Dc]);
    sq[d] = xq; sk[d] = xk;
    __syncthreads();

    float yq = xq, yk = xk;
    if (d < ROTc) {
        int i = d >> 1;
        float inv = powf(10000.f, -(float)(2 * i) / (float)ROTc);
        float ang = (float)pos[bs] * inv;
        float sn, cs;
        sincosf(ang, &sn, &cs);
        float oq = (d & 1) ? sq[d - 1] : sq[d + 1];
        float ok = (d & 1) ? sk[d - 1] : sk[d + 1];
        yq = (d & 1) ? (xq * cs + oq * sn) : (xq * cs - oq * sn);
        yk = (d & 1) ? (xk * cs + ok * sn) : (xk * cs - ok * sn);
    }

    float ssq = yq * yq, ssk = yk * yk;
#pragma unroll
    for (int o = 16; o; o >>= 1) {
        ssq += __shfl_xor_sync(0xffffffffu, ssq, o);
        ssk += __shfl_xor_sync(0xffffffffu, ssk, o);
    }
    if ((d & 31) == 0) { redq[d >> 5] = ssq; redk[d >> 5] = ssk; }
    __syncthreads();
    float nq = sqrtf(redq[0] + redq[1] + redq[2] + redq[3]);
    float nk = sqrtf(redk[0] + redk[1] + redk[2] + redk[3]);

    float keep = (mask[bs] == 0.f) ? 1.f : 0.f;
    Qh[outb] = __float2half(yq / fmaxf(nq, 1e-12f) * keep);
    Kh[outb] = __float2half(yk / fmaxf(nk, 1e-12f) * keep);

    float expo = 1.f / (1.f + expf(-nc[h]));
    float scale = keep / fmaxf(powf(cnt[bs], expo), 1.f);
    Vh[outb] = __float2half(xv * scale);
}

// ---------------------------------------------------------------------------
// fp16 tensor-core causal attention (R8/R10 proven version: 64q tile)
// ---------------------------------------------------------------------------
#define AQ2 64
#define ATT_QS 0u
#define ATT_KS0 16384u
#define ATT_KS1 32768u
#define ATT_VS0 49152u
#define ATT_VS1 65536u
#define ATT_PS 81920u
#define ATT_SMEM 90112

__global__ __launch_bounds__(256) void attn_fp16(
    const half* __restrict__ Qh, const half* __restrict__ Kh,
    const half* __restrict__ Vh, half* __restrict__ O)
{
    extern __shared__ half smh[];
    const uint32_t S0 = smem_u32(smh);

    const int bh = blockIdx.y;
    const int b = bh >> 4;
    const int h = bh & (Hc - 1);
    const int qt = gridDim.x - 1 - blockIdx.x;   // big tiles first

    const int tid  = threadIdx.x;
    const int warp = tid >> 5, lane = tid & 31;
    const int gid  = lane >> 2, tig = lane & 3;
    const int wq   = (warp >> 1) * 16;
    const int wk   = (warp & 1) * 32;
    const int wd   = (warp & 1) * 64;

    const uint32_t kbuf[2] = {ATT_KS0, ATT_KS1};
    const uint32_t vbuf[2] = {ATT_VS0, ATT_VS1};

    int srow[4], sphy[4];
#pragma unroll
    for (int i = 0; i < 4; i++) {
        int cid = tid + 256 * i;
        srow[i] = cid >> 4;
        sphy[i] = (cid & 15) ^ (srow[i] & 7);
    }

    const half* Qg = Qh + ((size_t)(b * Sc + qt * AQ2)) * Dc + h * HDc;

#pragma unroll
    for (int i = 0; i < 4; i++) {
        int c = (tid + 256 * i) & 15;
        cp16(S0 + ATT_QS + srow[i] * 256 + sphy[i] * 16,
             Qg + (size_t)srow[i] * Dc + c * 8);
    }
    {
        const half* Kg = Kh + ((size_t)(b * Sc)) * Dc + h * HDc;
        const half* Vg = Vh + ((size_t)(b * Sc)) * Dc + h * HDc;
#pragma unroll
        for (int i = 0; i < 4; i++) {
            int c = (tid + 256 * i) & 15;
            cp16(S0 + kbuf[0] + srow[i] * 256 + sphy[i] * 16,
                 Kg + (size_t)srow[i] * Dc + c * 8);
            cp16(S0 + vbuf[0] + srow[i] * 256 + sphy[i] * 16,
                 Vg + (size_t)srow[i] * Dc + c * 8);
        }
    }
    CP_COMMIT();

    float oacc[8][4];
#pragma unroll
    for (int i = 0; i < 8; i++)
#pragma unroll
        for (int l = 0; l < 4; l++) oacc[i][l] = 0.f;

    const int arow1 = wq + (lane & 7) + ((lane >> 3) & 1) * 8;
    const int ax1 = arow1 & 7;
    const int chi = lane >> 4;

    for (int kt = 0; kt <= qt; kt++) {
        cp_wait<0>();
        __syncthreads();

        if (kt + 1 <= qt) {
            const int s = kt + 1;
            const uint32_t kb = kbuf[s & 1], vb = vbuf[s & 1];
            const half* Kg = Kh + ((size_t)(b * Sc + s * AQ2)) * Dc + h * HDc;
            const half* Vg = Vh + ((size_t)(b * Sc + s * AQ2)) * Dc + h * HDc;
#pragma unroll
            for (int i = 0; i < 4; i++) {
                int c = (tid + 256 * i) & 15;
                cp16(S0 + kb + srow[i] * 256 + sphy[i] * 16,
                     Kg + (size_t)srow[i] * Dc + c * 8);
                cp16(S0 + vb + srow[i] * 256 + sphy[i] * 16,
                     Vg + (size_t)srow[i] * Dc + c * 8);
            }
            CP_COMMIT();
        }

        const uint32_t kbs = S0 + kbuf[kt & 1];
        const uint32_t vbs = S0 + vbuf[kt & 1];

        float pacc[4][4];
#pragma unroll
        for (int i = 0; i < 4; i++)
#pragma unroll
            for (int l = 0; l < 4; l++) pacc[i][l] = 0.f;

#pragma unroll
        for (int ks = 0; ks < 8; ks++) {
            const int c0 = ks * 2 + chi;
            uint32_t a[4];
            ldm_x4(a, S0 + ATT_QS + arow1 * 256 + ((c0 ^ ax1) * 16));
#pragma unroll
            for (int n2 = 0; n2 < 2; n2++) {
                int brow = wk + n2 * 16 + (lane & 7) + ((lane >> 3) & 1) * 8;
                uint32_t r[4];
                ldm_x4(r, kbs + brow * 256 + ((c0 ^ (brow & 7)) * 16));
                mma_fp16(pacc[2*n2],   a, r[0], r[2]);
                mma_fp16(pacc[2*n2+1], a, r[1], r[3]);
            }
        }

        const bool diag = (kt == qt);
#pragma unroll
        for (int nt = 0; nt < 4; nt++) {
            int kl0 = wk + nt * 8 + tig * 2;
            int q0 = wq + gid, q1 = q0 + 8;
            float v00 = pacc[nt][0], v01 = pacc[nt][1];
            float v10 = pacc[nt][2], v11 = pacc[nt][3];
            if (diag) {
                if (kl0     > q0) v00 = 0.f;
                if (kl0 + 1 > q0) v01 = 0.f;
                if (kl0     > q1) v10 = 0.f;
                if (kl0 + 1 > q1) v11 = 0.f;
            }
            int chunk = kl0 >> 3;
            sts32(S0 + ATT_PS + q0 * 128 + ((chunk ^ (q0 & 7)) * 16) + tig * 4,
                  pack_h2(v00, v01));
            sts32(S0 + ATT_PS + q1 * 128 + ((chunk ^ (q1 & 7)) * 16) + tig * 4,
                  pack_h2(v10, v11));
        }
        __syncthreads();

#pragma unroll
        for (int ks = 0; ks < 4; ks++) {
            const int ca = ks * 2 + chi;
            uint32_t a[4];
            ldm_x4(a, S0 + ATT_PS + arow1 * 128 + ((ca ^ ax1) * 16));
            const int vrow = ks * 16 + (lane & 7) + ((lane >> 3) & 1) * 8;
            const int vx = vrow & 7;
#pragma unroll
            for (int j = 0; j < 4; j++) {
                int cd = (wd >> 3) + j * 2 + chi;
                uint32_t r[4];
                ldm_x4t(r, vbs + vrow * 256 + ((cd ^ vx) * 16));
                mma_fp16(oacc[2*j],   a, r[0], r[1]);
                mma_fp16(oacc[2*j+1], a, r[2], r[3]);
            }
        }
        __syncthreads();
    }

    half* Og = O + ((size_t)(b * Sc + qt * AQ2)) * Dc + h * HDc;
    int q0 = wq + gid, q1 = q0 + 8;
#pragma unroll
    for (int nt = 0; nt < 8; nt++) {
        int d0 = wd + nt * 8 + tig * 2;
        *(uint32_t*)&Og[(size_t)q0 * Dc + d0] = pack_h2(oacc[nt][0], oacc[nt][1]);
        *(uint32_t*)&Og[(size_t)q1 * Dc + d0] = pack_h2(oacc[nt][2], oacc[nt][3]);
    }
}

// ---------------------------------------------------------------------------
// launch
// ---------------------------------------------------------------------------
extern "C" void kernel_launch(void* const* d_in, const int* in_sizes, int n_in,
                              void* d_out, int out_size)
{
    const float* hs   = (const float*)d_in[0];
    const float* mask = (const float*)d_in[1];
    const int*   pos  = (const int*)  d_in[2];
    const float* Wq   = (const float*)d_in[3];
    const float* Wk   = (const float*)d_in[4];
    const float* Wv   = (const float*)d_in[5];
    const float* Wo   = (const float*)d_in[6];
    const float* nc   = (const float*)d_in[7];
    float* out = (float*)d_out;

    float *cnt;
    half *hsh, *wh, *woh, *qkvh, *abh, *qh, *kh, *vh;
    cudaGetSymbolAddress((void**)&cnt,  g_cnt);
    cudaGetSymbolAddress((void**)&hsh,  g_hsh);
    cudaGetSymbolAddress((void**)&wh,   g_wh);
    cudaGetSymbolAddress((void**)&woh,  g_woh);
    cudaGetSymbolAddress((void**)&qkvh, g_qkvh);
    cudaGetSymbolAddress((void**)&abh,  g_abh);
    cudaGetSymbolAddress((void**)&qh,   g_qh);
    cudaGetSymbolAddress((void**)&kh,   g_kh);
    cudaGetSymbolAddress((void**)&vh,   g_vh);

    cudaFuncSetAttribute(gemm_fp16_h,
                         cudaFuncAttributeMaxDynamicSharedMemorySize, GEMM_SMEM);
    cudaFuncSetAttribute(gemm_fp16_f,
                         cudaFuncAttributeMaxDynamicSharedMemorySize, GEMM_SMEM);
    cudaFuncSetAttribute(attn_fp16,
                         cudaFuncAttributeMaxDynamicSharedMemorySize, ATT_SMEM);

    const int nHS = Mc * Dc;
    const int nW  = Dc * Dc;

    counts_kernel<<<Bc, 256>>>(mask, cnt);

    f32_to_f16<<<nHS / (256 * 8), 256>>>(hs, hsh, nHS);
    f32_to_f16<<<nW  / (256 * 8), 256>>>(Wq, wh, nW);
    f32_to_f16<<<nW  / (256 * 8), 256>>>(Wk, wh + (size_t)Dc * Dc, nW);
    f32_to_f16<<<nW  / (256 * 8), 256>>>(Wv, wh + (size_t)2 * Dc * Dc, nW);
    f32_to_f16<<<nW  / (256 * 8), 256>>>(Wo, woh, nW);

    // fused QKV GEMM: [M][2048] x [6144][2048]^T -> [M][6144] fp16
    dim3 qkvGrid(NQKV / GBN, Mc / GBM);   // (24, 32)
    gemm_fp16_h<<<qkvGrid, 256, GEMM_SMEM>>>(hsh, wh, qkvh, Mc, NQKV, Dc);

    const int nrows = Bc * Sc * Hc;
    post_qkv_kernel<<<nrows, 128>>>(qkvh, qh, kh, vh, mask, pos, cnt, nc);

    dim3 attnGrid(Sc / AQ2, Bc * Hc);     // (32, 32)
    attn_fp16<<<attnGrid, 256, ATT_SMEM>>>(qh, kh, vh, abh);

    dim3 oGrid(Dc / GBN, Mc / GBM);       // (8, 32)
    gemm_fp16_f<<<oGrid, 256, GEMM_SMEM>>>(abh, woh, out, Mc, Dc, Dc);
}

// round 13
// speedup vs baseline: 1.0652x; 1.0328x over previous
#include <cuda_runtime.h>
#include <cuda_fp16.h>
#include <math.h>
#include <stdint.h>

// Problem constants
#define Bc   2
#define Sc   2048
#define Dc   2048
#define Hc   16
#define HDc  128
#define ROTc 64
#define Mc   (Bc*Sc)
#define NQKV (3*Dc)   // 6144

// ---------------------------------------------------------------------------
// Scratch
// ---------------------------------------------------------------------------
__device__ float g_cnt[Bc*Sc];
__device__ half  g_hsh [(size_t)Mc*Dc];
__device__ half  g_wh  [(size_t)NQKV*Dc];   // packed [Wq;Wk;Wv]
__device__ half  g_woh [(size_t)Dc*Dc];
__device__ half  g_qkvh[(size_t)Mc*NQKV];
__device__ half  g_abh [(size_t)Mc*Dc];
__device__ half  g_qh  [(size_t)Mc*Dc];
__device__ half  g_kh  [(size_t)Mc*Dc];
__device__ half  g_vh  [(size_t)Mc*Dc];

// ---------------------------------------------------------------------------
// helpers
// ---------------------------------------------------------------------------
__device__ __forceinline__ uint32_t smem_u32(const void* p) {
    uint32_t a;
    asm("{ .reg .u64 t; cvta.to.shared.u64 t, %1; cvt.u32.u64 %0, t; }"
        : "=r"(a) : "l"(p));
    return a;
}
__device__ __forceinline__ uint32_t pack_h2(float lo, float hi) {
    half2 h = __floats2half2_rn(lo, hi);
    return *(uint32_t*)&h;
}
__device__ __forceinline__ void cp16(uint32_t dst, const void* src) {
    asm volatile("cp.async.cg.shared.global [%0], [%1], 16;" :: "r"(dst), "l"(src));
}
#define CP_COMMIT() asm volatile("cp.async.commit_group;" ::: "memory")
template<int N>
__device__ __forceinline__ void cp_wait() {
    asm volatile("cp.async.wait_group %0;" :: "n"(N) : "memory");
}
__device__ __forceinline__ void ldm_x4(uint32_t r[4], uint32_t addr) {
    asm volatile("ldmatrix.sync.aligned.m8n8.x4.shared.b16 {%0,%1,%2,%3}, [%4];"
        : "=r"(r[0]), "=r"(r[1]), "=r"(r[2]), "=r"(r[3]) : "r"(addr));
}
__device__ __forceinline__ void ldm_x4t(uint32_t r[4], uint32_t addr) {
    asm volatile("ldmatrix.sync.aligned.m8n8.x4.trans.shared.b16 {%0,%1,%2,%3}, [%4];"
        : "=r"(r[0]), "=r"(r[1]), "=r"(r[2]), "=r"(r[3]) : "r"(addr));
}
__device__ __forceinline__ void sts32(uint32_t addr, uint32_t v) {
    asm volatile("st.shared.b32 [%0], %1;" :: "r"(addr), "r"(v));
}
__device__ __forceinline__ void mma_fp16(float c[4], const uint32_t a[4],
                                         const uint32_t b0, const uint32_t b1) {
    asm volatile(
        "mma.sync.aligned.m16n8k16.row.col.f32.f16.f16.f32 "
        "{%0,%1,%2,%3}, {%4,%5,%6,%7}, {%8,%9}, {%0,%1,%2,%3};"
        : "+f"(c[0]), "+f"(c[1]), "+f"(c[2]), "+f"(c[3])
        : "r"(a[0]), "r"(a[1]), "r"(a[2]), "r"(a[3]),
          "r"(b0), "r"(b1));
}

// ---------------------------------------------------------------------------
// merged fp32 -> fp16 conversion: hs (8M) + Wq/Wk/Wv -> packed wh + Wo -> woh
// 24M elements, 8 per thread; region dispatch on global element index.
// ---------------------------------------------------------------------------
#define CVT_TOTAL (24*1024*1024)
#define CVT_BLOCKS (CVT_TOTAL / (256*8))

__global__ __launch_bounds__(256) void convert_all(
    const float* __restrict__ hs, const float* __restrict__ Wq,
    const float* __restrict__ Wk, const float* __restrict__ Wv,
    const float* __restrict__ Wo,
    half* __restrict__ hsh, half* __restrict__ wh, half* __restrict__ woh)
{
    const int i = (blockIdx.x * 256 + threadIdx.x) * 8;
    const float* src;
    half* dst;
    const int HS_N = Mc * Dc;          // 8M
    const int W_N  = Dc * Dc;          // 4M
    if (i < HS_N) {
        src = hs + i; dst = hsh + i;
    } else {
        int j = i - HS_N;
        int r = j / W_N;
        int off = j - r * W_N;
        const float* srcs[4] = {Wq, Wk, Wv, Wo};
        src = srcs[r] + off;
        dst = (r < 3) ? (wh + (size_t)r * W_N + off) : (woh + off);
    }
    float4 a = *(const float4*)src;
    float4 b = *(const float4*)(src + 4);
    uint4 u = make_uint4(pack_h2(a.x, a.y), pack_h2(a.z, a.w),
                         pack_h2(b.x, b.y), pack_h2(b.z, b.w));
    *(uint4*)dst = u;
}

// ---------------------------------------------------------------------------
// fp16 GEMM core: CTA tile 128x256, warp tile 64x64, BK=32,
// cp.async 3-stage pipeline (R10-proven).
// Swizzle: 64B rows, 16B chunk c at phys = c ^ ((row>>1)&3).
// ---------------------------------------------------------------------------
#define GBM 128
#define GBN 256
#define GBK 32
#define GA_BUF 8192u
#define GB_BUF 16384u
#define STAGES 3
#define GB_BASE ((uint32_t)STAGES * GA_BUF)             // 24576
#define GEMM_SMEM (GB_BASE + (uint32_t)STAGES * GB_BUF) // 73728

template <typename OutT>
__device__ __forceinline__ void gemm_fp16_body(
    const half* __restrict__ A, const half* __restrict__ W,
    OutT* __restrict__ C, int M, int N, int K)
{
    extern __shared__ half gsm[];
    const uint32_t S0 = smem_u32(gsm);

    const int tid  = threadIdx.x;
    const int warp = tid >> 5, lane = tid & 31;
    const int gid  = lane >> 2, tig = lane & 3;
    const int wm   = (warp >> 2) * 64, wn = (warp & 3) * 64;
    const int bm   = blockIdx.y * GBM,  bn = blockIdx.x * GBN;

    int aRow[2], aC[2]; uint32_t aDst[2];
#pragma unroll
    for (int i = 0; i < 2; i++) {
        int cid = tid + 256 * i;
        aRow[i] = cid >> 2; aC[i] = cid & 3;
        int phys = aC[i] ^ ((aRow[i] >> 1) & 3);
        aDst[i] = S0 + aRow[i] * 64 + phys * 16;
    }
    int bRow[4], bC[4]; uint32_t bDst[4];
#pragma unroll
    for (int i = 0; i < 4; i++) {
        int cid = tid + 256 * i;
        bRow[i] = cid >> 2; bC[i] = cid & 3;
        int phys = bC[i] ^ ((bRow[i] >> 1) & 3);
        bDst[i] = S0 + GB_BASE + bRow[i] * 64 + phys * 16;
    }

    uint32_t arow[4]; int axor[4];
    const int ahi = lane >> 4;
#pragma unroll
    for (int mt = 0; mt < 4; mt++) {
        int r = wm + 16 * mt + (lane & 7) + ((lane >> 3) & 1) * 8;
        arow[mt] = S0 + r * 64;
        axor[mt] = (r >> 1) & 3;
    }
    uint32_t brow[4]; int bxor[4];
    const int bhi = (lane >> 3) & 1;
#pragma unroll
    for (int n2 = 0; n2 < 4; n2++) {
        int r = wn + n2 * 16 + (lane & 7) + ((lane >> 4) & 1) * 8;
        brow[n2] = S0 + GB_BASE + r * 64;
        bxor[n2] = (r >> 1) & 3;
    }

    float acc[4][8][4];
#pragma unroll
    for (int i = 0; i < 4; i++)
#pragma unroll
        for (int j = 0; j < 8; j++)
#pragma unroll
            for (int l = 0; l < 4; l++) acc[i][j][l] = 0.f;

    const int NT = K / GBK;

    // prologue: stages 0,1
#pragma unroll
    for (int s = 0; s < 2; s++) {
#pragma unroll
        for (int i = 0; i < 2; i++)
            cp16(aDst[i] + s * GA_BUF,
                 A + (size_t)(bm + aRow[i]) * K + s * GBK + aC[i] * 8);
#pragma unroll
        for (int i = 0; i < 4; i++)
            cp16(bDst[i] + s * GB_BUF,
                 W + (size_t)(bn + bRow[i]) * K + s * GBK + bC[i] * 8);
        CP_COMMIT();
    }

    for (int kt = 0; kt < NT; kt++) {
        if (kt == NT - 1) cp_wait<0>(); else cp_wait<1>();
        __syncthreads();

        if (kt + 2 < NT) {
            const int s = kt + 2;
            const uint32_t sa = (uint32_t)(s % STAGES) * GA_BUF;
            const uint32_t sb = (uint32_t)(s % STAGES) * GB_BUF;
#pragma unroll
            for (int i = 0; i < 2; i++)
                cp16(aDst[i] + sa,
                     A + (size_t)(bm + aRow[i]) * K + s * GBK + aC[i] * 8);
#pragma unroll
            for (int i = 0; i < 4; i++)
                cp16(bDst[i] + sb,
                     W + (size_t)(bn + bRow[i]) * K + s * GBK + bC[i] * 8);
            CP_COMMIT();
        }

        const uint32_t aofs = (uint32_t)(kt % STAGES) * GA_BUF;
        const uint32_t bofs = (uint32_t)(kt % STAGES) * GB_BUF;
#pragma unroll
        for (int ks = 0; ks < 2; ks++) {
            uint32_t af[4][4], bf[8][2];
#pragma unroll
            for (int mt = 0; mt < 4; mt++) {
                int chunk = 2 * ks + ahi;
                ldm_x4(af[mt], arow[mt] + aofs + (uint32_t)((chunk ^ axor[mt]) * 16));
            }
#pragma unroll
            for (int n2 = 0; n2 < 4; n2++) {
                int chunk = 2 * ks + bhi;
                uint32_t r[4];
                ldm_x4(r, brow[n2] + bofs + (uint32_t)((chunk ^ bxor[n2]) * 16));
                bf[n2*2][0] = r[0]; bf[n2*2][1] = r[1];
                bf[n2*2+1][0] = r[2]; bf[n2*2+1][1] = r[3];
            }
#pragma unroll
            for (int mt = 0; mt < 4; mt++)
#pragma unroll
                for (int nt = 0; nt < 8; nt++)
                    mma_fp16(acc[mt][nt], af[mt], bf[nt][0], bf[nt][1]);
        }
    }

    // epilogue
#pragma unroll
    for (int mt = 0; mt < 4; mt++) {
        int r0 = bm + wm + mt * 16 + gid;
#pragma unroll
        for (int nt = 0; nt < 8; nt++) {
            int c0 = bn + wn + nt * 8 + tig * 2;
            if (sizeof(OutT) == 2) {
                half* Ch = (half*)C;
                *(uint32_t*)&Ch[(size_t)r0 * N + c0]       = pack_h2(acc[mt][nt][0], acc[mt][nt][1]);
                *(uint32_t*)&Ch[(size_t)(r0 + 8) * N + c0] = pack_h2(acc[mt][nt][2], acc[mt][nt][3]);
            } else {
                float* Cf = (float*)C;
                *(float2*)&Cf[(size_t)r0 * N + c0]       = make_float2(acc[mt][nt][0], acc[mt][nt][1]);
                *(float2*)&Cf[(size_t)(r0 + 8) * N + c0] = make_float2(acc[mt][nt][2], acc[mt][nt][3]);
            }
        }
    }
}

__global__ __launch_bounds__(256) void gemm_fp16_h(
    const half* __restrict__ A, const half* __restrict__ W,
    half* __restrict__ C, int M, int N, int K)
{ gemm_fp16_body<half>(A, W, C, M, N, K); }

__global__ __launch_bounds__(256) void gemm_fp16_f(
    const half* __restrict__ A, const half* __restrict__ W,
    float* __restrict__ C, int M, int N, int K)
{ gemm_fp16_body<float>(A, W, C, M, N, K); }

// ---------------------------------------------------------------------------
// counts
// ---------------------------------------------------------------------------
__global__ __launch_bounds__(256) void counts_kernel(
    const float* __restrict__ mask, float* __restrict__ cnt)
{
    __shared__ float part[256];
    const int b = blockIdx.x;
    const int t = threadIdx.x;
    const int base = b * Sc;

    float local[8];
    float sum = 0.f;
#pragma unroll
    for (int j = 0; j < 8; j++) {
        int s = t * 8 + j;
        float kp = (mask[base + s] == 0.f) ? 1.f : 0.f;
        sum += kp;
        local[j] = sum;
    }
    part[t] = sum;
    __syncthreads();
    if (t == 0) {
        float run = 0.f;
        for (int i = 0; i < 256; i++) { float tmp = part[i]; part[i] = run; run += tmp; }
    }
    __syncthreads();
    float off = part[t];
#pragma unroll
    for (int j = 0; j < 8; j++)
        cnt[base + t * 8 + j] = off + local[j];
}

// ---------------------------------------------------------------------------
// fused post-projection: reads fused fp16 QKV [M][6144], RoPE+L2norm+mask
// for Q/K, scale V; writes fp16 Q/K/V [M][2048]
// ---------------------------------------------------------------------------
__global__ __launch_bounds__(128) void post_qkv_kernel(
    const half* __restrict__ QKV,
    half* __restrict__ Qh, half* __restrict__ Kh, half* __restrict__ Vh,
    const float* __restrict__ mask, const int* __restrict__ pos,
    const float* __restrict__ cnt, const float* __restrict__ nc)
{
    const int bsh = blockIdx.x;
    const int h  = bsh & (Hc - 1);
    const int bs = bsh >> 4;
    const int d = threadIdx.x;
    const size_t inb = (size_t)bs * NQKV + h * HDc + d;
    const size_t outb = (size_t)bs * Dc + h * HDc + d;

    __shared__ float sq[HDc], sk[HDc];
    __shared__ float redq[4], redk[4];

    float xq = __half2float(QKV[inb]);
    float xk = __half2float(QKV[inb + Dc]);
    float xv = __half2float(QKV[inb + 2 * Dc]);
    sq[d] = xq; sk[d] = xk;
    __syncthreads();

    float yq = xq, yk = xk;
    if (d < ROTc) {
        int i = d >> 1;
        float inv = powf(10000.f, -(float)(2 * i) / (float)ROTc);
        float ang = (float)pos[bs] * inv;
        float sn, cs;
        sincosf(ang, &sn, &cs);
        float oq = (d & 1) ? sq[d - 1] : sq[d + 1];
        float ok = (d & 1) ? sk[d - 1] : sk[d + 1];
        yq = (d & 1) ? (xq * cs + oq * sn) : (xq * cs - oq * sn);
        yk = (d & 1) ? (xk * cs + ok * sn) : (xk * cs - ok * sn);
    }

    float ssq = yq * yq, ssk = yk * yk;
#pragma unroll
    for (int o = 16; o; o >>= 1) {
        ssq += __shfl_xor_sync(0xffffffffu, ssq, o);
        ssk += __shfl_xor_sync(0xffffffffu, ssk, o);
    }
    if ((d & 31) == 0) { redq[d >> 5] = ssq; redk[d >> 5] = ssk; }
    __syncthreads();
    float nq = sqrtf(redq[0] + redq[1] + redq[2] + redq[3]);
    float nk = sqrtf(redk[0] + redk[1] + redk[2] + redk[3]);

    float keep = (mask[bs] == 0.f) ? 1.f : 0.f;
    Qh[outb] = __float2half(yq / fmaxf(nq, 1e-12f) * keep);
    Kh[outb] = __float2half(yk / fmaxf(nk, 1e-12f) * keep);

    float expo = 1.f / (1.f + expf(-nc[h]));
    float scale = keep / fmaxf(powf(cnt[bs], expo), 1.f);
    Vh[outb] = __float2half(xv * scale);
}

// ---------------------------------------------------------------------------
// fp16 tensor-core causal attention (R10 proven, minus redundant end-sync)
// ---------------------------------------------------------------------------
#define AQ2 64
#define ATT_QS 0u
#define ATT_KS0 16384u
#define ATT_KS1 32768u
#define ATT_VS0 49152u
#define ATT_VS1 65536u
#define ATT_PS 81920u
#define ATT_SMEM 90112

__global__ __launch_bounds__(256) void attn_fp16(
    const half* __restrict__ Qh, const half* __restrict__ Kh,
    const half* __restrict__ Vh, half* __restrict__ O)
{
    extern __shared__ half smh[];
    const uint32_t S0 = smem_u32(smh);

    const int bh = blockIdx.y;
    const int b = bh >> 4;
    const int h = bh & (Hc - 1);
    const int qt = gridDim.x - 1 - blockIdx.x;   // big tiles first

    const int tid  = threadIdx.x;
    const int warp = tid >> 5, lane = tid & 31;
    const int gid  = lane >> 2, tig = lane & 3;
    const int wq   = (warp >> 1) * 16;
    const int wk   = (warp & 1) * 32;
    const int wd   = (warp & 1) * 64;

    const uint32_t kbuf[2] = {ATT_KS0, ATT_KS1};
    const uint32_t vbuf[2] = {ATT_VS0, ATT_VS1};

    int srow[4], sphy[4];
#pragma unroll
    for (int i = 0; i < 4; i++) {
        int cid = tid + 256 * i;
        srow[i] = cid >> 4;
        sphy[i] = (cid & 15) ^ (srow[i] & 7);
    }

    const half* Qg = Qh + ((size_t)(b * Sc + qt * AQ2)) * Dc + h * HDc;

#pragma unroll
    for (int i = 0; i < 4; i++) {
        int c = (tid + 256 * i) & 15;
        cp16(S0 + ATT_QS + srow[i] * 256 + sphy[i] * 16,
             Qg + (size_t)srow[i] * Dc + c * 8);
    }
    {
        const half* Kg = Kh + ((size_t)(b * Sc)) * Dc + h * HDc;
        const half* Vg = Vh + ((size_t)(b * Sc)) * Dc + h * HDc;
#pragma unroll
        for (int i = 0; i < 4; i++) {
            int c = (tid + 256 * i) & 15;
            cp16(S0 + kbuf[0] + srow[i] * 256 + sphy[i] * 16,
                 Kg + (size_t)srow[i] * Dc + c * 8);
            cp16(S0 + vbuf[0] + srow[i] * 256 + sphy[i] * 16,
                 Vg + (size_t)srow[i] * Dc + c * 8);
        }
    }
    CP_COMMIT();

    float oacc[8][4];
#pragma unroll
    for (int i = 0; i < 8; i++)
#pragma unroll
        for (int l = 0; l < 4; l++) oacc[i][l] = 0.f;

    const int arow1 = wq + (lane & 7) + ((lane >> 3) & 1) * 8;
    const int ax1 = arow1 & 7;
    const int chi = lane >> 4;

    for (int kt = 0; kt <= qt; kt++) {
        cp_wait<0>();
        __syncthreads();   // joins prev iter's phase2 AND cp.async data ready

        if (kt + 1 <= qt) {
            const int s = kt + 1;
            const uint32_t kb = kbuf[s & 1], vb = vbuf[s & 1];
            const half* Kg = Kh + ((size_t)(b * Sc + s * AQ2)) * Dc + h * HDc;
            const half* Vg = Vh + ((size_t)(b * Sc + s * AQ2)) * Dc + h * HDc;
#pragma unroll
            for (int i = 0; i < 4; i++) {
                int c = (tid + 256 * i) & 15;
                cp16(S0 + kb + srow[i] * 256 + sphy[i] * 16,
                     Kg + (size_t)srow[i] * Dc + c * 8);
                cp16(S0 + vb + srow[i] * 256 + sphy[i] * 16,
                     Vg + (size_t)srow[i] * Dc + c * 8);
            }
            CP_COMMIT();
        }

        const uint32_t kbs = S0 + kbuf[kt & 1];
        const uint32_t vbs = S0 + vbuf[kt & 1];

        float pacc[4][4];
#pragma unroll
        for (int i = 0; i < 4; i++)
#pragma unroll
            for (int l = 0; l < 4; l++) pacc[i][l] = 0.f;

#pragma unroll
        for (int ks = 0; ks < 8; ks++) {
            const int c0 = ks * 2 + chi;
            uint32_t a[4];
            ldm_x4(a, S0 + ATT_QS + arow1 * 256 + ((c0 ^ ax1) * 16));
#pragma unroll
            for (int n2 = 0; n2 < 2; n2++) {
                int brow = wk + n2 * 16 + (lane & 7) + ((lane >> 3) & 1) * 8;
                uint32_t r[4];
                ldm_x4(r, kbs + brow * 256 + ((c0 ^ (brow & 7)) * 16));
                mma_fp16(pacc[2*n2],   a, r[0], r[2]);
                mma_fp16(pacc[2*n2+1], a, r[1], r[3]);
            }
        }

        const bool diag = (kt == qt);
#pragma unroll
        for (int nt = 0; nt < 4; nt++) {
            int kl0 = wk + nt * 8 + tig * 2;
            int q0 = wq + gid, q1 = q0 + 8;
            float v00 = pacc[nt][0], v01 = pacc[nt][1];
            float v10 = pacc[nt][2], v11 = pacc[nt][3];
            if (diag) {
                if (kl0     > q0) v00 = 0.f;
                if (kl0 + 1 > q0) v01 = 0.f;
                if (kl0     > q1) v10 = 0.f;
                if (kl0 + 1 > q1) v11 = 0.f;
            }
            int chunk = kl0 >> 3;
            sts32(S0 + ATT_PS + q0 * 128 + ((chunk ^ (q0 & 7)) * 16) + tig * 4,
                  pack_h2(v00, v01));
            sts32(S0 + ATT_PS + q1 * 128 + ((chunk ^ (q1 & 7)) * 16) + tig * 4,
                  pack_h2(v10, v11));
        }
        __syncthreads();   // P produced -> consumed (cross-warp within pair)

#pragma unroll
        for (int ks = 0; ks < 4; ks++) {
            const int ca = ks * 2 + chi;
            uint32_t a[4];
            ldm_x4(a, S0 + ATT_PS + arow1 * 128 + ((ca ^ ax1) * 16));
            const int vrow = ks * 16 + (lane & 7) + ((lane >> 3) & 1) * 8;
            const int vx = vrow & 7;
#pragma unroll
            for (int j = 0; j < 4; j++) {
                int cd = (wd >> 3) + j * 2 + chi;
                uint32_t r[4];
                ldm_x4t(r, vbs + vrow * 256 + ((cd ^ vx) * 16));
                mma_fp16(oacc[2*j],   a, r[0], r[1]);
                mma_fp16(oacc[2*j+1], a, r[2], r[3]);
            }
        }
        // no end sync: next iter's top __syncthreads subsumes it
    }

    half* Og = O + ((size_t)(b * Sc + qt * AQ2)) * Dc + h * HDc;
    int q0 = wq + gid, q1 = q0 + 8;
#pragma unroll
    for (int nt = 0; nt < 8; nt++) {
        int d0 = wd + nt * 8 + tig * 2;
        *(uint32_t*)&Og[(size_t)q0 * Dc + d0] = pack_h2(oacc[nt][0], oacc[nt][1]);
        *(uint32_t*)&Og[(size_t)q1 * Dc + d0] = pack_h2(oacc[nt][2], oacc[nt][3]);
    }
}

// ---------------------------------------------------------------------------
// launch
// ---------------------------------------------------------------------------
extern "C" void kernel_launch(void* const* d_in, const int* in_sizes, int n_in,
                              void* d_out, int out_size)
{
    const float* hs   = (const float*)d_in[0];
    const float* mask = (const float*)d_in[1];
    const int*   pos  = (const int*)  d_in[2];
    const float* Wq   = (const float*)d_in[3];
    const float* Wk   = (const float*)d_in[4];
    const float* Wv   = (const float*)d_in[5];
    const float* Wo   = (const float*)d_in[6];
    const float* nc   = (const float*)d_in[7];
    float* out = (float*)d_out;

    float *cnt;
    half *hsh, *wh, *woh, *qkvh, *abh, *qh, *kh, *vh;
    cudaGetSymbolAddress((void**)&cnt,  g_cnt);
    cudaGetSymbolAddress((void**)&hsh,  g_hsh);
    cudaGetSymbolAddress((void**)&wh,   g_wh);
    cudaGetSymbolAddress((void**)&woh,  g_woh);
    cudaGetSymbolAddress((void**)&qkvh, g_qkvh);
    cudaGetSymbolAddress((void**)&abh,  g_abh);
    cudaGetSymbolAddress((void**)&qh,   g_qh);
    cudaGetSymbolAddress((void**)&kh,   g_kh);
    cudaGetSymbolAddress((void**)&vh,   g_vh);

    cudaFuncSetAttribute(gemm_fp16_h,
                         cudaFuncAttributeMaxDynamicSharedMemorySize, GEMM_SMEM);
    cudaFuncSetAttribute(gemm_fp16_f,
                         cudaFuncAttributeMaxDynamicSharedMemorySize, GEMM_SMEM);
    cudaFuncSetAttribute(attn_fp16,
                         cudaFuncAttributeMaxDynamicSharedMemorySize, ATT_SMEM);

    counts_kernel<<<Bc, 256>>>(mask, cnt);

    convert_all<<<CVT_BLOCKS, 256>>>(hs, Wq, Wk, Wv, Wo, hsh, wh, woh);

    // fused QKV GEMM: [M][2048] x [6144][2048]^T -> [M][6144] fp16
    dim3 qkvGrid(NQKV / GBN, Mc / GBM);   // (24, 32)
    gemm_fp16_h<<<qkvGrid, 256, GEMM_SMEM>>>(hsh, wh, qkvh, Mc, NQKV, Dc);

    const int nrows = Bc * Sc * Hc;
    post_qkv_kernel<<<nrows, 128>>>(qkvh, qh, kh, vh, mask, pos, cnt, nc);

    dim3 attnGrid(Sc / AQ2, Bc * Hc);     // (32, 32)
    attn_fp16<<<attnGrid, 256, ATT_SMEM>>>(qh, kh, vh, abh);

    dim3 oGrid(Dc / GBN, Mc / GBM);       // (8, 32)
    gemm_fp16_f<<<oGrid, 256, GEMM_SMEM>>>(abh, woh, out, Mc, Dc, Dc);
}

// round 14
// speedup vs baseline: 1.0769x; 1.0110x over previous
#include <cuda_runtime.h>
#include <cuda_fp16.h>
#include <math.h>
#include <stdint.h>

// Problem constants
#define Bc   2
#define Sc   2048
#define Dc   2048
#define Hc   16
#define HDc  128
#define ROTc 64
#define Mc   (Bc*Sc)
#define NQKV (3*Dc)   // 6144

// ---------------------------------------------------------------------------
// Scratch
// ---------------------------------------------------------------------------
__device__ float  g_cnt[Bc*Sc];
__device__ float2 g_rope[(size_t)Bc*Sc*32];
__device__ half   g_hsh [(size_t)Mc*Dc];
__device__ half   g_wh  [(size_t)NQKV*Dc];   // packed [Wq;Wk;Wv]
__device__ half   g_woh [(size_t)Dc*Dc];
__device__ half   g_qkvh[(size_t)Mc*NQKV];
__device__ half   g_abh [(size_t)Mc*Dc];
__device__ half   g_qh  [(size_t)Mc*Dc];
__device__ half   g_kh  [(size_t)Mc*Dc];
__device__ half   g_vh  [(size_t)Mc*Dc];

// ---------------------------------------------------------------------------
// helpers
// ---------------------------------------------------------------------------
__device__ __forceinline__ uint32_t smem_u32(const void* p) {
    uint32_t a;
    asm("{ .reg .u64 t; cvta.to.shared.u64 t, %1; cvt.u32.u64 %0, t; }"
        : "=r"(a) : "l"(p));
    return a;
}
__device__ __forceinline__ uint32_t pack_h2(float lo, float hi) {
    half2 h = __floats2half2_rn(lo, hi);
    return *(uint32_t*)&h;
}
__device__ __forceinline__ void cp16(uint32_t dst, const void* src) {
    asm volatile("cp.async.cg.shared.global [%0], [%1], 16;" :: "r"(dst), "l"(src));
}
#define CP_COMMIT() asm volatile("cp.async.commit_group;" ::: "memory")
template<int N>
__device__ __forceinline__ void cp_wait() {
    asm volatile("cp.async.wait_group %0;" :: "n"(N) : "memory");
}
__device__ __forceinline__ void ldm_x4(uint32_t r[4], uint32_t addr) {
    asm volatile("ldmatrix.sync.aligned.m8n8.x4.shared.b16 {%0,%1,%2,%3}, [%4];"
        : "=r"(r[0]), "=r"(r[1]), "=r"(r[2]), "=r"(r[3]) : "r"(addr));
}
__device__ __forceinline__ void ldm_x4t(uint32_t r[4], uint32_t addr) {
    asm volatile("ldmatrix.sync.aligned.m8n8.x4.trans.shared.b16 {%0,%1,%2,%3}, [%4];"
        : "=r"(r[0]), "=r"(r[1]), "=r"(r[2]), "=r"(r[3]) : "r"(addr));
}
__device__ __forceinline__ void sts32(uint32_t addr, uint32_t v) {
    asm volatile("st.shared.b32 [%0], %1;" :: "r"(addr), "r"(v));
}
__device__ __forceinline__ void mma_fp16(float c[4], const uint32_t a[4],
                                         const uint32_t b0, const uint32_t b1) {
    asm volatile(
        "mma.sync.aligned.m16n8k16.row.col.f32.f16.f16.f32 "
        "{%0,%1,%2,%3}, {%4,%5,%6,%7}, {%8,%9}, {%0,%1,%2,%3};"
        : "+f"(c[0]), "+f"(c[1]), "+f"(c[2]), "+f"(c[3])
        : "r"(a[0]), "r"(a[1]), "r"(a[2]), "r"(a[3]),
          "r"(b0), "r"(b1));
}

// ---------------------------------------------------------------------------
// merged fp32 -> fp16 conversion: hs (8M) + Wq/Wk/Wv -> packed wh + Wo -> woh
// ---------------------------------------------------------------------------
#define CVT_TOTAL (24*1024*1024)
#define CVT_BLOCKS (CVT_TOTAL / (256*8))

__global__ __launch_bounds__(256) void convert_all(
    const float* __restrict__ hs, const float* __restrict__ Wq,
    const float* __restrict__ Wk, const float* __restrict__ Wv,
    const float* __restrict__ Wo,
    half* __restrict__ hsh, half* __restrict__ wh, half* __restrict__ woh)
{
    const int i = (blockIdx.x * 256 + threadIdx.x) * 8;
    const float* src;
    half* dst;
    const int HS_N = Mc * Dc;
    const int W_N  = Dc * Dc;
    if (i < HS_N) {
        src = hs + i; dst = hsh + i;
    } else {
        int j = i - HS_N;
        int r = j / W_N;
        int off = j - r * W_N;
        const float* srcs[4] = {Wq, Wk, Wv, Wo};
        src = srcs[r] + off;
        dst = (r < 3) ? (wh + (size_t)r * W_N + off) : (woh + off);
    }
    float4 a = *(const float4*)src;
    float4 b = *(const float4*)(src + 4);
    uint4 u = make_uint4(pack_h2(a.x, a.y), pack_h2(a.z, a.w),
                         pack_h2(b.x, b.y), pack_h2(b.z, b.w));
    *(uint4*)dst = u;
}

// ---------------------------------------------------------------------------
// rope table: sin/cos per (b*s, i) -- same math as reference (powf+sincosf)
// ---------------------------------------------------------------------------
__global__ __launch_bounds__(256) void rope_table_kernel(
    const int* __restrict__ pos, float2* __restrict__ tab)
{
    int idx = blockIdx.x * 256 + threadIdx.x;   // < Bc*Sc*32
    int bs = idx >> 5, i = idx & 31;
    float inv = powf(10000.f, -(float)(2 * i) / (float)ROTc);
    float ang = (float)pos[bs] * inv;
    float sn, cs;
    sincosf(ang, &sn, &cs);
    tab[idx] = make_float2(sn, cs);
}

// ---------------------------------------------------------------------------
// fp16 GEMM core: CTA tile 128x256, warp tile 64x64, BK=32,
// cp.async 3-stage pipeline (R10-proven).
// ---------------------------------------------------------------------------
#define GBM 128
#define GBN 256
#define GBK 32
#define GA_BUF 8192u
#define GB_BUF 16384u
#define STAGES 3
#define GB_BASE ((uint32_t)STAGES * GA_BUF)
#define GEMM_SMEM (GB_BASE + (uint32_t)STAGES * GB_BUF)   // 73728

template <typename OutT>
__device__ __forceinline__ void gemm_fp16_body(
    const half* __restrict__ A, const half* __restrict__ W,
    OutT* __restrict__ C, int M, int N, int K)
{
    extern __shared__ half gsm[];
    const uint32_t S0 = smem_u32(gsm);

    const int tid  = threadIdx.x;
    const int warp = tid >> 5, lane = tid & 31;
    const int gid  = lane >> 2, tig = lane & 3;
    const int wm   = (warp >> 2) * 64, wn = (warp & 3) * 64;
    const int bm   = blockIdx.y * GBM,  bn = blockIdx.x * GBN;

    int aRow[2], aC[2]; uint32_t aDst[2];
#pragma unroll
    for (int i = 0; i < 2; i++) {
        int cid = tid + 256 * i;
        aRow[i] = cid >> 2; aC[i] = cid & 3;
        int phys = aC[i] ^ ((aRow[i] >> 1) & 3);
        aDst[i] = S0 + aRow[i] * 64 + phys * 16;
    }
    int bRow[4], bC[4]; uint32_t bDst[4];
#pragma unroll
    for (int i = 0; i < 4; i++) {
        int cid = tid + 256 * i;
        bRow[i] = cid >> 2; bC[i] = cid & 3;
        int phys = bC[i] ^ ((bRow[i] >> 1) & 3);
        bDst[i] = S0 + GB_BASE + bRow[i] * 64 + phys * 16;
    }

    uint32_t arow[4]; int axor[4];
    const int ahi = lane >> 4;
#pragma unroll
    for (int mt = 0; mt < 4; mt++) {
        int r = wm + 16 * mt + (lane & 7) + ((lane >> 3) & 1) * 8;
        arow[mt] = S0 + r * 64;
        axor[mt] = (r >> 1) & 3;
    }
    uint32_t brow[4]; int bxor[4];
    const int bhi = (lane >> 3) & 1;
#pragma unroll
    for (int n2 = 0; n2 < 4; n2++) {
        int r = wn + n2 * 16 + (lane & 7) + ((lane >> 4) & 1) * 8;
        brow[n2] = S0 + GB_BASE + r * 64;
        bxor[n2] = (r >> 1) & 3;
    }

    float acc[4][8][4];
#pragma unroll
    for (int i = 0; i < 4; i++)
#pragma unroll
        for (int j = 0; j < 8; j++)
#pragma unroll
            for (int l = 0; l < 4; l++) acc[i][j][l] = 0.f;

    const int NT = K / GBK;

#pragma unroll
    for (int s = 0; s < 2; s++) {
#pragma unroll
        for (int i = 0; i < 2; i++)
            cp16(aDst[i] + s * GA_BUF,
                 A + (size_t)(bm + aRow[i]) * K + s * GBK + aC[i] * 8);
#pragma unroll
        for (int i = 0; i < 4; i++)
            cp16(bDst[i] + s * GB_BUF,
                 W + (size_t)(bn + bRow[i]) * K + s * GBK + bC[i] * 8);
        CP_COMMIT();
    }

    for (int kt = 0; kt < NT; kt++) {
        if (kt == NT - 1) cp_wait<0>(); else cp_wait<1>();
        __syncthreads();

        if (kt + 2 < NT) {
            const int s = kt + 2;
            const uint32_t sa = (uint32_t)(s % STAGES) * GA_BUF;
            const uint32_t sb = (uint32_t)(s % STAGES) * GB_BUF;
#pragma unroll
            for (int i = 0; i < 2; i++)
                cp16(aDst[i] + sa,
                     A + (size_t)(bm + aRow[i]) * K + s * GBK + aC[i] * 8);
#pragma unroll
            for (int i = 0; i < 4; i++)
                cp16(bDst[i] + sb,
                     W + (size_t)(bn + bRow[i]) * K + s * GBK + bC[i] * 8);
            CP_COMMIT();
        }

        const uint32_t aofs = (uint32_t)(kt % STAGES) * GA_BUF;
        const uint32_t bofs = (uint32_t)(kt % STAGES) * GB_BUF;
#pragma unroll
        for (int ks = 0; ks < 2; ks++) {
            uint32_t af[4][4], bf[8][2];
#pragma unroll
            for (int mt = 0; mt < 4; mt++) {
                int chunk = 2 * ks + ahi;
                ldm_x4(af[mt], arow[mt] + aofs + (uint32_t)((chunk ^ axor[mt]) * 16));
            }
#pragma unroll
            for (int n2 = 0; n2 < 4; n2++) {
                int chunk = 2 * ks + bhi;
                uint32_t r[4];
                ldm_x4(r, brow[n2] + bofs + (uint32_t)((chunk ^ bxor[n2]) * 16));
                bf[n2*2][0] = r[0]; bf[n2*2][1] = r[1];
                bf[n2*2+1][0] = r[2]; bf[n2*2+1][1] = r[3];
            }
#pragma unroll
            for (int mt = 0; mt < 4; mt++)
#pragma unroll
                for (int nt = 0; nt < 8; nt++)
                    mma_fp16(acc[mt][nt], af[mt], bf[nt][0], bf[nt][1]);
        }
    }

#pragma unroll
    for (int mt = 0; mt < 4; mt++) {
        int r0 = bm + wm + mt * 16 + gid;
#pragma unroll
        for (int nt = 0; nt < 8; nt++) {
            int c0 = bn + wn + nt * 8 + tig * 2;
            if (sizeof(OutT) == 2) {
                half* Ch = (half*)C;
                *(uint32_t*)&Ch[(size_t)r0 * N + c0]       = pack_h2(acc[mt][nt][0], acc[mt][nt][1]);
                *(uint32_t*)&Ch[(size_t)(r0 + 8) * N + c0] = pack_h2(acc[mt][nt][2], acc[mt][nt][3]);
            } else {
                float* Cf = (float*)C;
                *(float2*)&Cf[(size_t)r0 * N + c0]       = make_float2(acc[mt][nt][0], acc[mt][nt][1]);
                *(float2*)&Cf[(size_t)(r0 + 8) * N + c0] = make_float2(acc[mt][nt][2], acc[mt][nt][3]);
            }
        }
    }
}

__global__ __launch_bounds__(256) void gemm_fp16_h(
    const half* __restrict__ A, const half* __restrict__ W,
    half* __restrict__ C, int M, int N, int K)
{ gemm_fp16_body<half>(A, W, C, M, N, K); }

__global__ __launch_bounds__(256) void gemm_fp16_f(
    const half* __restrict__ A, const half* __restrict__ W,
    float* __restrict__ C, int M, int N, int K)
{ gemm_fp16_body<float>(A, W, C, M, N, K); }

// ---------------------------------------------------------------------------
// counts
// ---------------------------------------------------------------------------
__global__ __launch_bounds__(256) void counts_kernel(
    const float* __restrict__ mask, float* __restrict__ cnt)
{
    __shared__ float part[256];
    const int b = blockIdx.x;
    const int t = threadIdx.x;
    const int base = b * Sc;

    float local[8];
    float sum = 0.f;
#pragma unroll
    for (int j = 0; j < 8; j++) {
        int s = t * 8 + j;
        float kp = (mask[base + s] == 0.f) ? 1.f : 0.f;
        sum += kp;
        local[j] = sum;
    }
    part[t] = sum;
    __syncthreads();
    if (t == 0) {
        float run = 0.f;
        for (int i = 0; i < 256; i++) { float tmp = part[i]; part[i] = run; run += tmp; }
    }
    __syncthreads();
    float off = part[t];
#pragma unroll
    for (int j = 0; j < 8; j++)
        cnt[base + t * 8 + j] = off + local[j];
}

// ---------------------------------------------------------------------------
// fused post-projection (transcendental-free hot path):
// reads fused fp16 QKV, rope table; RoPE+L2norm+mask Q/K, scale V; fp16 out
// ---------------------------------------------------------------------------
__global__ __launch_bounds__(128) void post_qkv_kernel(
    const half* __restrict__ QKV, const float2* __restrict__ rope,
    half* __restrict__ Qh, half* __restrict__ Kh, half* __restrict__ Vh,
    const float* __restrict__ mask,
    const float* __restrict__ cnt, const float* __restrict__ nc)
{
    const int bsh = blockIdx.x;
    const int h  = bsh & (Hc - 1);
    const int bs = bsh >> 4;
    const int d = threadIdx.x;
    const size_t inb = (size_t)bs * NQKV + h * HDc + d;
    const size_t outb = (size_t)bs * Dc + h * HDc + d;

    __shared__ float redq[4], redk[4];

    float xq = __half2float(QKV[inb]);
    float xk = __half2float(QKV[inb + Dc]);
    float xv = __half2float(QKV[inb + 2 * Dc]);

    float yq = xq, yk = xk;
    if (d < ROTc) {
        float2 sc = rope[bs * 32 + (d >> 1)];
        float oq = __shfl_xor_sync(0xffffffffu, xq, 1);
        float ok = __shfl_xor_sync(0xffffffffu, xk, 1);
        yq = (d & 1) ? fmaf(xq, sc.y, oq * sc.x) : fmaf(xq, sc.y, -oq * sc.x);
        yk = (d & 1) ? fmaf(xk, sc.y, ok * sc.x) : fmaf(xk, sc.y, -ok * sc.x);
    } else {
        // keep shuffles uniform across the warp (d>=64 warps don't enter)
    }

    float ssq = yq * yq, ssk = yk * yk;
#pragma unroll
    for (int o = 16; o; o >>= 1) {
        ssq += __shfl_xor_sync(0xffffffffu, ssq, o);
        ssk += __shfl_xor_sync(0xffffffffu, ssk, o);
    }
    if ((d & 31) == 0) { redq[d >> 5] = ssq; redk[d >> 5] = ssk; }
    __syncthreads();
    float nq = sqrtf(redq[0] + redq[1] + redq[2] + redq[3]);
    float nk = sqrtf(redk[0] + redk[1] + redk[2] + redk[3]);

    float keep = (mask[bs] == 0.f) ? 1.f : 0.f;
    Qh[outb] = __float2half(yq / fmaxf(nq, 1e-12f) * keep);
    Kh[outb] = __float2half(yk / fmaxf(nk, 1e-12f) * keep);

    float expo = 1.f / (1.f + __expf(-nc[h]));
    float c = cnt[bs];
    float p = (c > 0.f) ? exp2f(expo * log2f(c)) : 0.f;
    float scale = keep / fmaxf(p, 1.f);
    Vh[outb] = __float2half(xv * scale);
}

// ---------------------------------------------------------------------------
// fp16 tensor-core causal attention (R13 proven)
// ---------------------------------------------------------------------------
#define AQ2 64
#define ATT_QS 0u
#define ATT_KS0 16384u
#define ATT_KS1 32768u
#define ATT_VS0 49152u
#define ATT_VS1 65536u
#define ATT_PS 81920u
#define ATT_SMEM 90112

__global__ __launch_bounds__(256) void attn_fp16(
    const half* __restrict__ Qh, const half* __restrict__ Kh,
    const half* __restrict__ Vh, half* __restrict__ O)
{
    extern __shared__ half smh[];
    const uint32_t S0 = smem_u32(smh);

    const int bh = blockIdx.y;
    const int b = bh >> 4;
    const int h = bh & (Hc - 1);
    const int qt = gridDim.x - 1 - blockIdx.x;

    const int tid  = threadIdx.x;
    const int warp = tid >> 5, lane = tid & 31;
    const int gid  = lane >> 2, tig = lane & 3;
    const int wq   = (warp >> 1) * 16;
    const int wk   = (warp & 1) * 32;
    const int wd   = (warp & 1) * 64;

    const uint32_t kbuf[2] = {ATT_KS0, ATT_KS1};
    const uint32_t vbuf[2] = {ATT_VS0, ATT_VS1};

    int srow[4], sphy[4];
#pragma unroll
    for (int i = 0; i < 4; i++) {
        int cid = tid + 256 * i;
        srow[i] = cid >> 4;
        sphy[i] = (cid & 15) ^ (srow[i] & 7);
    }

    const half* Qg = Qh + ((size_t)(b * Sc + qt * AQ2)) * Dc + h * HDc;

#pragma unroll
    for (int i = 0; i < 4; i++) {
        int c = (tid + 256 * i) & 15;
        cp16(S0 + ATT_QS + srow[i] * 256 + sphy[i] * 16,
             Qg + (size_t)srow[i] * Dc + c * 8);
    }
    {
        const half* Kg = Kh + ((size_t)(b * Sc)) * Dc + h * HDc;
        const half* Vg = Vh + ((size_t)(b * Sc)) * Dc + h * HDc;
#pragma unroll
        for (int i = 0; i < 4; i++) {
            int c = (tid + 256 * i) & 15;
            cp16(S0 + kbuf[0] + srow[i] * 256 + sphy[i] * 16,
                 Kg + (size_t)srow[i] * Dc + c * 8);
            cp16(S0 + vbuf[0] + srow[i] * 256 + sphy[i] * 16,
                 Vg + (size_t)srow[i] * Dc + c * 8);
        }
    }
    CP_COMMIT();

    float oacc[8][4];
#pragma unroll
    for (int i = 0; i < 8; i++)
#pragma unroll
        for (int l = 0; l < 4; l++) oacc[i][l] = 0.f;

    const int arow1 = wq + (lane & 7) + ((lane >> 3) & 1) * 8;
    const int ax1 = arow1 & 7;
    const int chi = lane >> 4;

    for (int kt = 0; kt <= qt; kt++) {
        cp_wait<0>();
        __syncthreads();

        if (kt + 1 <= qt) {
            const int s = kt + 1;
            const uint32_t kb = kbuf[s & 1], vb = vbuf[s & 1];
            const half* Kg = Kh + ((size_t)(b * Sc + s * AQ2)) * Dc + h * HDc;
            const half* Vg = Vh + ((size_t)(b * Sc + s * AQ2)) * Dc + h * HDc;
#pragma unroll
            for (int i = 0; i < 4; i++) {
                int c = (tid + 256 * i) & 15;
                cp16(S0 + kb + srow[i] * 256 + sphy[i] * 16,
                     Kg + (size_t)srow[i] * Dc + c * 8);
                cp16(S0 + vb + srow[i] * 256 + sphy[i] * 16,
                     Vg + (size_t)srow[i] * Dc + c * 8);
            }
            CP_COMMIT();
        }

        const uint32_t kbs = S0 + kbuf[kt & 1];
        const uint32_t vbs = S0 + vbuf[kt & 1];

        float pacc[4][4];
#pragma unroll
        for (int i = 0; i < 4; i++)
#pragma unroll
            for (int l = 0; l < 4; l++) pacc[i][l] = 0.f;

#pragma unroll
        for (int ks = 0; ks < 8; ks++) {
            const int c0 = ks * 2 + chi;
            uint32_t a[4];
            ldm_x4(a, S0 + ATT_QS + arow1 * 256 + ((c0 ^ ax1) * 16));
#pragma unroll
            for (int n2 = 0; n2 < 2; n2++) {
                int brow = wk + n2 * 16 + (lane & 7) + ((lane >> 3) & 1) * 8;
                uint32_t r[4];
                ldm_x4(r, kbs + brow * 256 + ((c0 ^ (brow & 7)) * 16));
                mma_fp16(pacc[2*n2],   a, r[0], r[2]);
                mma_fp16(pacc[2*n2+1], a, r[1], r[3]);
            }
        }

        const bool diag = (kt == qt);
#pragma unroll
        for (int nt = 0; nt < 4; nt++) {
            int kl0 = wk + nt * 8 + tig * 2;
            int q0 = wq + gid, q1 = q0 + 8;
            float v00 = pacc[nt][0], v01 = pacc[nt][1];
            float v10 = pacc[nt][2], v11 = pacc[nt][3];
            if (diag) {
                if (kl0     > q0) v00 = 0.f;
                if (kl0 + 1 > q0) v01 = 0.f;
                if (kl0     > q1) v10 = 0.f;
                if (kl0 + 1 > q1) v11 = 0.f;
            }
            int chunk = kl0 >> 3;
            sts32(S0 + ATT_PS + q0 * 128 + ((chunk ^ (q0 & 7)) * 16) + tig * 4,
                  pack_h2(v00, v01));
            sts32(S0 + ATT_PS + q1 * 128 + ((chunk ^ (q1 & 7)) * 16) + tig * 4,
                  pack_h2(v10, v11));
        }
        __syncthreads();

#pragma unroll
        for (int ks = 0; ks < 4; ks++) {
            const int ca = ks * 2 + chi;
            uint32_t a[4];
            ldm_x4(a, S0 + ATT_PS + arow1 * 128 + ((ca ^ ax1) * 16));
            const int vrow = ks * 16 + (lane & 7) + ((lane >> 3) & 1) * 8;
            const int vx = vrow & 7;
#pragma unroll
            for (int j = 0; j < 4; j++) {
                int cd = (wd >> 3) + j * 2 + chi;
                uint32_t r[4];
                ldm_x4t(r, vbs + vrow * 256 + ((cd ^ vx) * 16));
                mma_fp16(oacc[2*j],   a, r[0], r[1]);
                mma_fp16(oacc[2*j+1], a, r[2], r[3]);
            }
        }
        // next iter's top __syncthreads subsumes the end sync
    }

    half* Og = O + ((size_t)(b * Sc + qt * AQ2)) * Dc + h * HDc;
    int q0 = wq + gid, q1 = q0 + 8;
#pragma unroll
    for (int nt = 0; nt < 8; nt++) {
        int d0 = wd + nt * 8 + tig * 2;
        *(uint32_t*)&Og[(size_t)q0 * Dc + d0] = pack_h2(oacc[nt][0], oacc[nt][1]);
        *(uint32_t*)&Og[(size_t)q1 * Dc + d0] = pack_h2(oacc[nt][2], oacc[nt][3]);
    }
}

// ---------------------------------------------------------------------------
// launch
// ---------------------------------------------------------------------------
extern "C" void kernel_launch(void* const* d_in, const int* in_sizes, int n_in,
                              void* d_out, int out_size)
{
    const float* hs   = (const float*)d_in[0];
    const float* mask = (const float*)d_in[1];
    const int*   pos  = (const int*)  d_in[2];
    const float* Wq   = (const float*)d_in[3];
    const float* Wk   = (const float*)d_in[4];
    const float* Wv   = (const float*)d_in[5];
    const float* Wo   = (const float*)d_in[6];
    const float* nc   = (const float*)d_in[7];
    float* out = (float*)d_out;

    float *cnt; float2 *rope;
    half *hsh, *wh, *woh, *qkvh, *abh, *qh, *kh, *vh;
    cudaGetSymbolAddress((void**)&cnt,  g_cnt);
    cudaGetSymbolAddress((void**)&rope, g_rope);
    cudaGetSymbolAddress((void**)&hsh,  g_hsh);
    cudaGetSymbolAddress((void**)&wh,   g_wh);
    cudaGetSymbolAddress((void**)&woh,  g_woh);
    cudaGetSymbolAddress((void**)&qkvh, g_qkvh);
    cudaGetSymbolAddress((void**)&abh,  g_abh);
    cudaGetSymbolAddress((void**)&qh,   g_qh);
    cudaGetSymbolAddress((void**)&kh,   g_kh);
    cudaGetSymbolAddress((void**)&vh,   g_vh);

    cudaFuncSetAttribute(gemm_fp16_h,
                         cudaFuncAttributeMaxDynamicSharedMemorySize, GEMM_SMEM);
    cudaFuncSetAttribute(gemm_fp16_f,
                         cudaFuncAttributeMaxDynamicSharedMemorySize, GEMM_SMEM);
    cudaFuncSetAttribute(attn_fp16,
                         cudaFuncAttributeMaxDynamicSharedMemorySize, ATT_SMEM);

    counts_kernel<<<Bc, 256>>>(mask, cnt);
    rope_table_kernel<<<(Bc * Sc * 32) / 256, 256>>>(pos, rope);

    convert_all<<<CVT_BLOCKS, 256>>>(hs, Wq, Wk, Wv, Wo, hsh, wh, woh);

    dim3 qkvGrid(NQKV / GBN, Mc / GBM);   // (24, 32)
    gemm_fp16_h<<<qkvGrid, 256, GEMM_SMEM>>>(hsh, wh, qkvh, Mc, NQKV, Dc);

    const int nrows = Bc * Sc * Hc;
    post_qkv_kernel<<<nrows, 128>>>(qkvh, rope, qh, kh, vh, mask, cnt, nc);

    dim3 attnGrid(Sc / AQ2, Bc * Hc);     // (32, 32)
    attn_fp16<<<attnGrid, 256, ATT_SMEM>>>(qh, kh, vh, abh);

    dim3 oGrid(Dc / GBN, Mc / GBM);       // (8, 32)
    gemm_fp16_f<<<oGrid, 256, GEMM_SMEM>>>(abh, woh, out, Mc, Dc, Dc);
}